// round 12
// baseline (speedup 1.0000x reference)
#include <cuda_runtime.h>
#include <cuda_fp16.h>
#include <cstdint>

#define HNUM 12
#define DHEAD 64
#define BATCH 4
#define LQ 512
#define LK 512
#define DMODEL 768
#define XSIZE (BATCH*LQ*DMODEL)

// ---------------- scratch (device globals; no runtime alloc) ----------------
__device__ __half g_Xh[2*XSIZE];                        // hidden | ctx as half
__device__ __half g_Wth[3][DMODEL*DMODEL];              // W transposed [n][k]
__device__ __half g_Qh[BATCH*HNUM*LQ*DHEAD];
__device__ __half g_Kh[BATCH*HNUM*LK*DHEAD];
__device__ __half g_Vth[(size_t)BATCH*HNUM*DHEAD*LK];   // [bh][d][tok]
__device__ float  g_S[(size_t)BATCH*HNUM*LQ*LK];        // unnormalized exp E
__device__ __half g_Ph[(size_t)BATCH*HNUM*LQ*LK];
__device__ float  g_PW[BATCH*HNUM*LQ*4];
__device__ float  g_QDP[BATCH*HNUM*LQ*4];
__device__ uint32_t g_arc8[BATCH*512*512/4];
__device__ float  g_lnk[3*DHEAD];
__device__ float  g_lnv[3*DHEAD];

__device__ __forceinline__ uint32_t h2_bits(__half2 h) {
    union { __half2 h; uint32_t u; } cvt;
    cvt.h = h;
    return cvt.u;
}

#define MMA_F16(d, a, b)                                                      \
    asm volatile("mma.sync.aligned.m16n8k16.row.col.f32.f16.f16.f32 "          \
        "{%0,%1,%2,%3}, {%4,%5,%6,%7}, {%8,%9}, {%0,%1,%2,%3};"                \
        : "+f"((d)[0]), "+f"((d)[1]), "+f"((d)[2]), "+f"((d)[3])               \
        : "r"((a)[0]), "r"((a)[1]), "r"((a)[2]), "r"((a)[3]),                  \
          "r"((b)[0]), "r"((b)[1]))

#define CP_ASYNC16(dst, src) \
    asm volatile("cp.async.cg.shared.global [%0], [%1], 16;" :: "r"(dst), "l"(src) : "memory")
#define CP_COMMIT() asm volatile("cp.async.commit_group;" ::: "memory")
#define CP_WAIT1()  asm volatile("cp.async.wait_group 1;" ::: "memory")
#define CP_WAIT0()  asm volatile("cp.async.wait_group 0;" ::: "memory")

// ---------------- K1: arc pack | X convert | W transpose-convert | LN -------
__global__ __launch_bounds__(256) void prep_kernel(
    const int* __restrict__ arc,
    const float* __restrict__ hidden, const float* __restrict__ ctx,
    const float* __restrict__ Wq, const float* __restrict__ Wk,
    const float* __restrict__ Wv,
    const float* __restrict__ dpk, const float* __restrict__ dpv,
    const float* __restrict__ kg, const float* __restrict__ kb,
    const float* __restrict__ vg, const float* __restrict__ vb) {
    int bx = blockIdx.x;
    int t = threadIdx.x;
    if (bx < 1024) {
        int i = bx * 256 + t;
        const int4 a = *(const int4*)&arc[i * 4];
        g_arc8[i] = (uint32_t)a.x | ((uint32_t)a.y << 8) |
                    ((uint32_t)a.z << 16) | ((uint32_t)a.w << 24);
        return;
    }
    if (bx < 4096) {
        bool is_h = bx < 2560;
        const float* src = is_h ? hidden : ctx;
        __half* dst = g_Xh + (is_h ? 0 : XSIZE);
        int i = ((bx - (is_h ? 1024 : 2560)) * 256 + t) * 4;
        float4 v = *(const float4*)&src[i];
        *(__half2*)&dst[i]     = __floats2half2_rn(v.x, v.y);
        *(__half2*)&dst[i + 2] = __floats2half2_rn(v.z, v.w);
        return;
    }
    if (bx < 5824) {
        __shared__ float tile[32][33];
        int wb = bx - 4096;
        int sel = wb / 576;
        int tl = wb % 576;
        int tx0 = (tl % 24) * 32, ty0 = (tl / 24) * 32;
        const float* W = (sel == 0) ? Wq : (sel == 1 ? Wk : Wv);
        __half* WT = g_Wth[sel];
        int tx = t & 31, ty = t >> 5;
        #pragma unroll
        for (int i = 0; i < 32; i += 8)
            tile[ty + i][tx] = W[(size_t)(ty0 + ty + i) * DMODEL + tx0 + tx];
        __syncthreads();
        #pragma unroll
        for (int i = 0; i < 32; i += 8)
            WT[(size_t)(tx0 + ty + i) * DMODEL + ty0 + tx] =
                __float2half_rn(tile[tx][ty + i]);
        return;
    }
    int w = t >> 5;
    int lane = t & 31;
    if (w >= 6) return;
    const float* src = (w < 3) ? dpk + w * DHEAD : dpv + (w - 3) * DHEAD;
    const float* g   = (w < 3) ? kg : vg;
    const float* be  = (w < 3) ? kb : vb;
    float* dst       = (w < 3) ? g_lnk + w * DHEAD : g_lnv + (w - 3) * DHEAD;
    float e0 = src[lane], e1 = src[lane + 32];
    float s = e0 + e1;
    #pragma unroll
    for (int o = 16; o; o >>= 1) s += __shfl_xor_sync(0xffffffffu, s, o);
    float mu = s * (1.0f / 64.0f);
    float d0 = e0 - mu, d1 = e1 - mu;
    float v = d0 * d0 + d1 * d1;
    #pragma unroll
    for (int o = 16; o; o >>= 1) v += __shfl_xor_sync(0xffffffffu, v, o);
    float rs = rsqrtf(v * (1.0f / 64.0f) + 1e-5f);
    dst[lane]      = d0 * rs * g[lane]      + be[lane];
    dst[lane + 32] = d1 * rs * g[lane + 32] + be[lane + 32];
}

// ---------------- K2: f16 mma.sync QKV GEMM ----------------------------------
#define GW 36
#define G_STAGE_W (128 * GW * 2)
#define GEMM_SMEM_BYTES (2 * G_STAGE_W * 4)

__global__ __launch_bounds__(256, 2) void qkv_gemm_f16_kernel(
    const float* __restrict__ bq, const float* __restrict__ bk,
    const float* __restrict__ bv) {
    extern __shared__ uint32_t sm32[];

    int sel = blockIdx.z;
    const __half* Xh = g_Xh + ((sel == 0) ? 0 : XSIZE);
    const __half* Wth = g_Wth[sel];
    const float* bias = (sel == 0) ? bq : (sel == 1 ? bk : bv);

    int m0 = blockIdx.x * 128;
    int n0 = blockIdx.y * 128;
    int t = threadIdx.x;
    int w = t >> 5;
    int lane = t & 31;
    int gid = lane >> 2;
    int tid4 = lane & 3;
    int wm = w >> 2;
    int wn = w & 3;

    auto load_chunk = [&](int c, int s) {
        int k0 = c * 64;
        uint32_t* sA = sm32 + s * G_STAGE_W;
        uint32_t* sB = sA + 128 * GW;
        #pragma unroll
        for (int it = 0; it < 4; it++) {
            int idx = it * 256 + t;
            int r = idx >> 3, c8 = idx & 7;
            uint32_t da = (uint32_t)__cvta_generic_to_shared(&sA[r * GW + c8 * 4]);
            CP_ASYNC16(da, (const char*)(Xh + (size_t)(m0 + r) * DMODEL + k0) + c8 * 16);
            uint32_t db = (uint32_t)__cvta_generic_to_shared(&sB[r * GW + c8 * 4]);
            CP_ASYNC16(db, (const char*)(Wth + (size_t)(n0 + r) * DMODEL + k0) + c8 * 16);
        }
        CP_COMMIT();
    };

    float acc[4][4][4];
    #pragma unroll
    for (int mt = 0; mt < 4; mt++)
        #pragma unroll
        for (int nt = 0; nt < 4; nt++)
            #pragma unroll
            for (int f = 0; f < 4; f++) acc[mt][nt][f] = 0.f;

    load_chunk(0, 0);
    load_chunk(1, 1);
    CP_WAIT1();
    __syncthreads();

    for (int c = 0; c < 12; c++) {
        int s = c & 1;
        const uint32_t* sA = sm32 + s * G_STAGE_W;
        const uint32_t* sB = sA + 128 * GW;
        #pragma unroll
        for (int ks = 0; ks < 4; ks++) {
            int o = ks * 8;
            uint32_t afr[4][4];
            #pragma unroll
            for (int mt = 0; mt < 4; mt++) {
                int r = wm * 64 + mt * 16 + gid;
                afr[mt][0] = sA[r * GW + tid4 + o];
                afr[mt][1] = sA[(r + 8) * GW + tid4 + o];
                afr[mt][2] = sA[r * GW + tid4 + 4 + o];
                afr[mt][3] = sA[(r + 8) * GW + tid4 + 4 + o];
            }
            #pragma unroll
            for (int nt = 0; nt < 4; nt++) {
                int n = wn * 32 + nt * 8 + gid;
                uint32_t bfr[2];
                bfr[0] = sB[n * GW + tid4 + o];
                bfr[1] = sB[n * GW + tid4 + 4 + o];
                #pragma unroll
                for (int mt = 0; mt < 4; mt++)
                    MMA_F16(acc[mt][nt], afr[mt], bfr);
            }
        }
        __syncthreads();
        if (c + 2 < 12) {
            load_chunk(c + 2, s);
            CP_WAIT1();
        } else {
            CP_WAIT0();
        }
        __syncthreads();
    }

    float bv2[4][2];
    #pragma unroll
    for (int nt = 0; nt < 4; nt++) {
        int col = n0 + wn * 32 + nt * 8 + tid4 * 2;
        bv2[nt][0] = bias[col];
        bv2[nt][1] = bias[col + 1];
    }
    #pragma unroll
    for (int mt = 0; mt < 4; mt++) {
        #pragma unroll
        for (int hf = 0; hf < 2; hf++) {
            int row = m0 + wm * 64 + mt * 16 + gid + hf * 8;
            int b = row >> 9, tok = row & 511;
            #pragma unroll
            for (int nt = 0; nt < 4; nt++) {
                int col = n0 + wn * 32 + nt * 8 + tid4 * 2;
                int head = col >> 6, dh = col & 63;
                float vx = acc[mt][nt][hf * 2 + 0] + bv2[nt][0];
                float vy = acc[mt][nt][hf * 2 + 1] + bv2[nt][1];
                if (sel == 2) {
                    size_t base = ((size_t)(b * HNUM + head) * 64 + dh) * 512 + tok;
                    g_Vth[base]       = __float2half_rn(vx);
                    g_Vth[base + 512] = __float2half_rn(vy);
                } else {
                    __half* Out = (sel == 0) ? g_Qh : g_Kh;
                    *(__half2*)&Out[((size_t)(b * HNUM + head) * 512 + tok) * 64 + dh] =
                        __floats2half2_rn(vx, vy);
                }
            }
        }
    }
}

// ---------------- K2b: qdp[row][r] = Q[row] . lnk[r] -------------------------
__global__ __launch_bounds__(256) void qdp_kernel() {
    int w = blockIdx.x * 8 + (threadIdx.x >> 5);    // 0..24575
    int lane = threadIdx.x & 31;
    const __half* Qrow = g_Qh + (size_t)w * 64;
    float q0v = __half2float(Qrow[lane]), q1v = __half2float(Qrow[lane + 32]);
    float s0 = q0v * g_lnk[lane]       + q1v * g_lnk[lane + 32];
    float s1 = q0v * g_lnk[64 + lane]  + q1v * g_lnk[96 + lane];
    float s2 = q0v * g_lnk[128 + lane] + q1v * g_lnk[160 + lane];
    #pragma unroll
    for (int o = 16; o; o >>= 1) {
        s0 += __shfl_xor_sync(0xffffffffu, s0, o);
        s1 += __shfl_xor_sync(0xffffffffu, s1, o);
        s2 += __shfl_xor_sync(0xffffffffu, s2, o);
    }
    if (lane == 0)
        *(float4*)&g_QDP[w * 4] = make_float4(s0, s1, s2, 0.f);
}

// ---------------- KA: E = exp(QK^T/8 + qdp[arc] + mask) ----------------------
#define QKW 36
#define QK_F32_OFF (2 * 128 * QKW)                 // after sQ,sK (words)
#define QK_SMEM_BYTES ((QK_F32_OFF + 128 + 512) * 4 + 16384)

__global__ __launch_bounds__(256, 2) void qk_kernel(const float* __restrict__ mask) {
    extern __shared__ uint32_t sm32[];
    uint32_t* sQ = sm32;
    uint32_t* sK = sm32 + 128 * QKW;
    float* sMask = (float*)(sm32 + QK_F32_OFF);
    float* sQdp  = sMask + 128;                    // [128][4]
    unsigned char* sArc = (unsigned char*)(sQdp + 512);   // [128][128]

    int bh = blockIdx.z;
    int b = bh / HNUM;
    int q0 = blockIdx.x * 128;
    int k0 = blockIdx.y * 128;
    int t = threadIdx.x;
    int w = t >> 5;
    int lane = t & 31;
    int gid = lane >> 2;
    int tid4 = lane & 3;
    int wm = w >> 2;
    int wn = w & 3;

    const __half* Qbase = g_Qh + ((size_t)bh * 512 + q0) * 64;
    const __half* Kbase = g_Kh + ((size_t)bh * 512 + k0) * 64;
    const char* Abase = (const char*)g_arc8 + ((size_t)(b * 512 + q0)) * 512 + k0;

    #pragma unroll
    for (int it = 0; it < 4; it++) {
        int idx = it * 256 + t;
        int r = idx >> 3, c = idx & 7;
        uint32_t dq = (uint32_t)__cvta_generic_to_shared(&sQ[r * QKW + c * 4]);
        CP_ASYNC16(dq, (const char*)(Qbase + (size_t)r * 64) + c * 16);
        uint32_t dk = (uint32_t)__cvta_generic_to_shared(&sK[r * QKW + c * 4]);
        CP_ASYNC16(dk, (const char*)(Kbase + (size_t)r * 64) + c * 16);
        uint32_t da = (uint32_t)__cvta_generic_to_shared(&sArc[r * 128 + c * 16]);
        CP_ASYNC16(da, Abase + (size_t)r * 512 + c * 16);
    }
    CP_COMMIT();
    if (t < 128) {
        sMask[t] = mask[b * 512 + k0 + t];
        *(float4*)&sQdp[t * 4] = *(const float4*)&g_QDP[((size_t)bh * 512 + q0 + t) * 4];
    }
    CP_WAIT0();
    __syncthreads();

    float acc[4][4][4];
    #pragma unroll
    for (int mt = 0; mt < 4; mt++)
        #pragma unroll
        for (int nt = 0; nt < 4; nt++)
            #pragma unroll
            for (int f = 0; f < 4; f++) acc[mt][nt][f] = 0.f;

    #pragma unroll
    for (int ks = 0; ks < 4; ks++) {
        int o = ks * 8;
        uint32_t afr[4][4];
        #pragma unroll
        for (int mt = 0; mt < 4; mt++) {
            int r = wm * 64 + mt * 16 + gid;
            afr[mt][0] = sQ[r * QKW + tid4 + o];
            afr[mt][1] = sQ[(r + 8) * QKW + tid4 + o];
            afr[mt][2] = sQ[r * QKW + tid4 + 4 + o];
            afr[mt][3] = sQ[(r + 8) * QKW + tid4 + 4 + o];
        }
        #pragma unroll
        for (int nt = 0; nt < 4; nt++) {
            int n = wn * 32 + nt * 8 + gid;
            uint32_t bfr[2];
            bfr[0] = sK[n * QKW + tid4 + o];
            bfr[1] = sK[n * QKW + tid4 + 4 + o];
            #pragma unroll
            for (int mt = 0; mt < 4; mt++)
                MMA_F16(acc[mt][nt], afr[mt], bfr);
        }
    }

    #pragma unroll
    for (int mt = 0; mt < 4; mt++) {
        #pragma unroll
        for (int hf = 0; hf < 2; hf++) {
            int rl = wm * 64 + mt * 16 + gid + hf * 8;
            float* Erow = g_S + ((size_t)bh * 512 + q0 + rl) * 512 + k0;
            #pragma unroll
            for (int nt = 0; nt < 4; nt++) {
                int lc = wn * 32 + nt * 8 + tid4 * 2;
                int a0 = sArc[rl * 128 + lc];
                int a1 = sArc[rl * 128 + lc + 1];
                float e0 = __expf(fmaf(acc[mt][nt][hf * 2 + 0], 0.125f,
                                       sQdp[rl * 4 + a0] + sMask[lc]));
                float e1 = __expf(fmaf(acc[mt][nt][hf * 2 + 1], 0.125f,
                                       sQdp[rl * 4 + a1] + sMask[lc + 1]));
                *(float2*)&Erow[lc] = make_float2(e0, e1);
            }
        }
    }
}

// ---------------- KB: slim normalize: sums + masses -> half P ----------------
__global__ __launch_bounds__(256) void softmax_kernel() {
    int bh = blockIdx.y;
    int b = bh / HNUM;
    int q = blockIdx.x * 8 + (threadIdx.x >> 5);
    int lane = threadIdx.x & 31;

    const float* Erow = g_S + ((size_t)bh * 512 + q) * 512;
    uint4 aw4 = *(const uint4*)&g_arc8[((size_t)(b * 512 + q)) * 128 + lane * 4];
    uint32_t aws[4] = {aw4.x, aw4.y, aw4.z, aw4.w};

    float x[16];
    float sum = 0.f, p1 = 0.f, p2 = 0.f;
    #pragma unroll
    for (int j = 0; j < 4; j++) {
        float4 ev = *(const float4*)&Erow[lane * 16 + j * 4];
        uint32_t aw = aws[j];
        int a0 = aw & 3, a1 = (aw >> 8) & 3, a2 = (aw >> 16) & 3, a3 = (aw >> 24) & 3;
        x[j*4+0] = ev.x; x[j*4+1] = ev.y; x[j*4+2] = ev.z; x[j*4+3] = ev.w;
        sum += ev.x + ev.y + ev.z + ev.w;
        p1 += ((a0 == 1) ? ev.x : 0.f) + ((a1 == 1) ? ev.y : 0.f)
            + ((a2 == 1) ? ev.z : 0.f) + ((a3 == 1) ? ev.w : 0.f);
        p2 += ((a0 == 2) ? ev.x : 0.f) + ((a1 == 2) ? ev.y : 0.f)
            + ((a2 == 2) ? ev.z : 0.f) + ((a3 == 2) ? ev.w : 0.f);
    }
    #pragma unroll
    for (int o = 16; o; o >>= 1) {
        sum += __shfl_xor_sync(0xffffffffu, sum, o);
        p1  += __shfl_xor_sync(0xffffffffu, p1, o);
        p2  += __shfl_xor_sync(0xffffffffu, p2, o);
    }
    float inv = 1.f / sum;

    __half* Prow = g_Ph + ((size_t)bh * 512 + q) * 512;
    uint4 o0, o1;
    o0.x = h2_bits(__floats2half2_rn(x[0] * inv,  x[1] * inv));
    o0.y = h2_bits(__floats2half2_rn(x[2] * inv,  x[3] * inv));
    o0.z = h2_bits(__floats2half2_rn(x[4] * inv,  x[5] * inv));
    o0.w = h2_bits(__floats2half2_rn(x[6] * inv,  x[7] * inv));
    o1.x = h2_bits(__floats2half2_rn(x[8] * inv,  x[9] * inv));
    o1.y = h2_bits(__floats2half2_rn(x[10] * inv, x[11] * inv));
    o1.z = h2_bits(__floats2half2_rn(x[12] * inv, x[13] * inv));
    o1.w = h2_bits(__floats2half2_rn(x[14] * inv, x[15] * inv));
    *(uint4*)&Prow[lane * 16]     = o0;
    *(uint4*)&Prow[lane * 16 + 8] = o1;

    if (lane == 0) {
        float p0 = sum - p1 - p2;
        *(float4*)&g_PW[((size_t)bh * 512 + q) * 4] =
            make_float4(p0 * inv, p1 * inv, p2 * inv, 0.f);
    }
}

// ---------------- KC: O = P V + pw . lnv  (f16 mma) --------------------------
#define PVW 20
#define PV_STAGE_W (64 * PVW + 64 * PVW)
#define PV_SMEM_BYTES (2 * PV_STAGE_W * 4)

__global__ __launch_bounds__(256, 4) void pv_kernel(float* __restrict__ out) {
    extern __shared__ uint32_t sm32[];

    int bh = blockIdx.y;
    int b = bh / HNUM, h = bh % HNUM;
    int q0 = blockIdx.x * 64;
    int t = threadIdx.x;
    int w = t >> 5;
    int lane = t & 31;
    int gid = lane >> 2;
    int tid4 = lane & 3;
    int wm = w >> 1;
    int wn = w & 1;

    const __half* Pbase = g_Ph + ((size_t)bh * 512 + q0) * 512;
    const __half* Vtbase = g_Vth + (size_t)bh * 64 * 512;

    auto load_chunk = [&](int c, int s) {
        int k0 = c * 32;
        uint32_t* sP = sm32 + s * PV_STAGE_W;
        uint32_t* sV = sP + 64 * PVW;
        int r = t >> 2, c4 = t & 3;
        uint32_t dp = (uint32_t)__cvta_generic_to_shared(&sP[r * PVW + c4 * 4]);
        CP_ASYNC16(dp, (const char*)(Pbase + (size_t)r * 512 + k0) + c4 * 16);
        uint32_t dv = (uint32_t)__cvta_generic_to_shared(&sV[r * PVW + c4 * 4]);
        CP_ASYNC16(dv, (const char*)(Vtbase + (size_t)r * 512 + k0) + c4 * 16);
        CP_COMMIT();
    };

    float acc[4][4];
    #pragma unroll
    for (int nt = 0; nt < 4; nt++)
        #pragma unroll
        for (int f = 0; f < 4; f++) acc[nt][f] = 0.f;

    load_chunk(0, 0);
    load_chunk(1, 1);
    CP_WAIT1();
    __syncthreads();

    for (int c = 0; c < 16; c++) {
        int s = c & 1;
        const uint32_t* sP = sm32 + s * PV_STAGE_W;
        const uint32_t* sV = sP + 64 * PVW;
        #pragma unroll
        for (int ks = 0; ks < 2; ks++) {
            int o = ks * 8;
            uint32_t afr[4];
            int r = wm * 16 + gid;
            afr[0] = sP[r * PVW + tid4 + o];
            afr[1] = sP[(r + 8) * PVW + tid4 + o];
            afr[2] = sP[r * PVW + tid4 + 4 + o];
            afr[3] = sP[(r + 8) * PVW + tid4 + 4 + o];
            #pragma unroll
            for (int nt = 0; nt < 4; nt++) {
                int n = wn * 32 + nt * 8 + gid;
                uint32_t bfr[2];
                bfr[0] = sV[n * PVW + tid4 + o];
                bfr[1] = sV[n * PVW + tid4 + 4 + o];
                MMA_F16(acc[nt], afr, bfr);
            }
        }
        __syncthreads();
        if (c + 2 < 16) {
            load_chunk(c + 2, s);
            CP_WAIT1();
        } else {
            CP_WAIT0();
        }
        __syncthreads();
    }

    int r0 = wm * 16 + gid, r1 = r0 + 8;
    float4 pw0 = *(float4*)&g_PW[((size_t)bh * 512 + q0 + r0) * 4];
    float4 pw1 = *(float4*)&g_PW[((size_t)bh * 512 + q0 + r1) * 4];
    #pragma unroll
    for (int nt = 0; nt < 4; nt++) {
        int col = wn * 32 + nt * 8 + tid4 * 2;
        float l0a = g_lnv[col],       l0b = g_lnv[col + 1];
        float l1a = g_lnv[64 + col],  l1b = g_lnv[64 + col + 1];
        float l2a = g_lnv[128 + col], l2b = g_lnv[128 + col + 1];
        float2 v0, v1;
        v0.x = acc[nt][0] + pw0.x * l0a + pw0.y * l1a + pw0.z * l2a;
        v0.y = acc[nt][1] + pw0.x * l0b + pw0.y * l1b + pw0.z * l2b;
        v1.x = acc[nt][2] + pw1.x * l0a + pw1.y * l1a + pw1.z * l2a;
        v1.y = acc[nt][3] + pw1.x * l0b + pw1.y * l1b + pw1.z * l2b;
        *(float2*)&out[(size_t)(b * 512 + q0 + r0) * 768 + h * 64 + col] = v0;
        *(float2*)&out[(size_t)(b * 512 + q0 + r1) * 768 + h * 64 + col] = v1;
    }
}

// ---------------- launcher ----------------------------------------------------
extern "C" void kernel_launch(void* const* d_in, const int* in_sizes, int n_in,
                              void* d_out, int out_size) {
    const float* hidden = (const float*)d_in[0];
    const float* ctx    = (const float*)d_in[1];
    const float* mask   = (const float*)d_in[2];
    const int*   arc    = (const int*)d_in[3];
    const float* Wq = (const float*)d_in[4];  const float* bq = (const float*)d_in[5];
    const float* Wk = (const float*)d_in[6];  const float* bk = (const float*)d_in[7];
    const float* Wv = (const float*)d_in[8];  const float* bv = (const float*)d_in[9];
    const float* dpk = (const float*)d_in[10]; const float* dpv = (const float*)d_in[11];
    const float* lkg = (const float*)d_in[12]; const float* lkb = (const float*)d_in[13];
    const float* lvg = (const float*)d_in[14]; const float* lvb = (const float*)d_in[15];
    float* out = (float*)d_out;

    prep_kernel<<<5825, 256>>>(arc, hidden, ctx, Wq, Wk, Wv,
                               dpk, dpv, lkg, lkb, lvg, lvb);

    cudaFuncSetAttribute(qkv_gemm_f16_kernel, cudaFuncAttributeMaxDynamicSharedMemorySize,
                         GEMM_SMEM_BYTES);
    qkv_gemm_f16_kernel<<<dim3(16, 6, 3), 256, GEMM_SMEM_BYTES>>>(bq, bk, bv);

    qdp_kernel<<<3072, 256>>>();

    cudaFuncSetAttribute(qk_kernel, cudaFuncAttributeMaxDynamicSharedMemorySize,
                         QK_SMEM_BYTES);
    qk_kernel<<<dim3(4, 4, 48), 256, QK_SMEM_BYTES>>>(mask);

    softmax_kernel<<<dim3(64, 48), 256>>>();

    cudaFuncSetAttribute(pv_kernel, cudaFuncAttributeMaxDynamicSharedMemorySize,
                         PV_SMEM_BYTES);
    pv_kernel<<<dim3(8, 48), 256, PV_SMEM_BYTES>>>(out);
}

// round 14
// speedup vs baseline: 1.0921x; 1.0921x over previous
#include <cuda_runtime.h>
#include <cuda_fp16.h>
#include <cstdint>

#define HNUM 12
#define DHEAD 64
#define BATCH 4
#define LQ 512
#define LK 512
#define DMODEL 768
#define XSIZE (BATCH*LQ*DMODEL)
#define NROWS (BATCH*HNUM*LQ)

// ---------------- scratch (device globals; no runtime alloc) ----------------
__device__ __half g_Xh[2*XSIZE];                        // hidden | ctx as half
__device__ __half g_Wth[3][DMODEL*DMODEL];              // W transposed [n][k]
__device__ __half g_Qh[BATCH*HNUM*LQ*DHEAD];
__device__ __half g_Kh[BATCH*HNUM*LK*DHEAD];
__device__ __half g_Vth[(size_t)BATCH*HNUM*DHEAD*LK];   // [bh][d][tok]
__device__ float  g_S[(size_t)BATCH*HNUM*LQ*LK];        // unnormalized exp E (f32)
__device__ float  g_SUM[NROWS*4];                       // {sum, p1, p2, 0}
__device__ float  g_QDP[NROWS*4];
__device__ uint32_t g_arc8[BATCH*512*512/4];
__device__ float  g_lnk[3*DHEAD];
__device__ float  g_lnv[3*DHEAD];

__device__ __forceinline__ uint32_t h2_bits(__half2 h) {
    union { __half2 h; uint32_t u; } cvt;
    cvt.h = h;
    return cvt.u;
}

#define MMA_F16(d, a, b)                                                      \
    asm volatile("mma.sync.aligned.m16n8k16.row.col.f32.f16.f16.f32 "          \
        "{%0,%1,%2,%3}, {%4,%5,%6,%7}, {%8,%9}, {%0,%1,%2,%3};"                \
        : "+f"((d)[0]), "+f"((d)[1]), "+f"((d)[2]), "+f"((d)[3])               \
        : "r"((a)[0]), "r"((a)[1]), "r"((a)[2]), "r"((a)[3]),                  \
          "r"((b)[0]), "r"((b)[1]))

#define CP_ASYNC16(dst, src) \
    asm volatile("cp.async.cg.shared.global [%0], [%1], 16;" :: "r"(dst), "l"(src) : "memory")
#define CP_COMMIT() asm volatile("cp.async.commit_group;" ::: "memory")
#define CP_WAIT1()  asm volatile("cp.async.wait_group 1;" ::: "memory")
#define CP_WAIT0()  asm volatile("cp.async.wait_group 0;" ::: "memory")

// ---------------- K1: arc pack | X cvt | W transpose | zero sums | LN --------
__global__ __launch_bounds__(256) void prep_kernel(
    const int* __restrict__ arc,
    const float* __restrict__ hidden, const float* __restrict__ ctx,
    const float* __restrict__ Wq, const float* __restrict__ Wk,
    const float* __restrict__ Wv,
    const float* __restrict__ dpk, const float* __restrict__ dpv,
    const float* __restrict__ kg, const float* __restrict__ kb,
    const float* __restrict__ vg, const float* __restrict__ vb) {
    int bx = blockIdx.x;
    int t = threadIdx.x;
    if (bx < 1024) {
        int i = bx * 256 + t;
        const int4 a = *(const int4*)&arc[i * 4];
        g_arc8[i] = (uint32_t)a.x | ((uint32_t)a.y << 8) |
                    ((uint32_t)a.z << 16) | ((uint32_t)a.w << 24);
        return;
    }
    if (bx < 4096) {
        bool is_h = bx < 2560;
        const float* src = is_h ? hidden : ctx;
        __half* dst = g_Xh + (is_h ? 0 : XSIZE);
        int i = ((bx - (is_h ? 1024 : 2560)) * 256 + t) * 4;
        float4 v = *(const float4*)&src[i];
        *(__half2*)&dst[i]     = __floats2half2_rn(v.x, v.y);
        *(__half2*)&dst[i + 2] = __floats2half2_rn(v.z, v.w);
        return;
    }
    if (bx < 5824) {
        __shared__ float tile[32][33];
        int wb = bx - 4096;
        int sel = wb / 576;
        int tl = wb % 576;
        int tx0 = (tl % 24) * 32, ty0 = (tl / 24) * 32;
        const float* W = (sel == 0) ? Wq : (sel == 1 ? Wk : Wv);
        __half* WT = g_Wth[sel];
        int tx = t & 31, ty = t >> 5;
        #pragma unroll
        for (int i = 0; i < 32; i += 8)
            tile[ty + i][tx] = W[(size_t)(ty0 + ty + i) * DMODEL + tx0 + tx];
        __syncthreads();
        #pragma unroll
        for (int i = 0; i < 32; i += 8)
            WT[(size_t)(tx0 + ty + i) * DMODEL + ty0 + tx] =
                __float2half_rn(tile[tx][ty + i]);
        return;
    }
    if (bx < 5920) {
        int i = (bx - 5824) * 256 + t;
        *(float4*)&g_SUM[i * 4] = make_float4(0.f, 0.f, 0.f, 0.f);
        return;
    }
    int w = t >> 5;
    int lane = t & 31;
    if (w >= 6) return;
    const float* src = (w < 3) ? dpk + w * DHEAD : dpv + (w - 3) * DHEAD;
    const float* g   = (w < 3) ? kg : vg;
    const float* be  = (w < 3) ? kb : vb;
    float* dst       = (w < 3) ? g_lnk + w * DHEAD : g_lnv + (w - 3) * DHEAD;
    float e0 = src[lane], e1 = src[lane + 32];
    float s = e0 + e1;
    #pragma unroll
    for (int o = 16; o; o >>= 1) s += __shfl_xor_sync(0xffffffffu, s, o);
    float mu = s * (1.0f / 64.0f);
    float d0 = e0 - mu, d1 = e1 - mu;
    float v = d0 * d0 + d1 * d1;
    #pragma unroll
    for (int o = 16; o; o >>= 1) v += __shfl_xor_sync(0xffffffffu, v, o);
    float rs = rsqrtf(v * (1.0f / 64.0f) + 1e-5f);
    dst[lane]      = d0 * rs * g[lane]      + be[lane];
    dst[lane + 32] = d1 * rs * g[lane + 32] + be[lane + 32];
}

// ---------------- K2: f16 mma.sync QKV GEMM ----------------------------------
#define GW 36
#define G_STAGE_W (128 * GW * 2)
#define GEMM_SMEM_BYTES (2 * G_STAGE_W * 4)

__global__ __launch_bounds__(256, 2) void qkv_gemm_f16_kernel(
    const float* __restrict__ bq, const float* __restrict__ bk,
    const float* __restrict__ bv) {
    extern __shared__ uint32_t sm32[];

    int sel = blockIdx.z;
    const __half* Xh = g_Xh + ((sel == 0) ? 0 : XSIZE);
    const __half* Wth = g_Wth[sel];
    const float* bias = (sel == 0) ? bq : (sel == 1 ? bk : bv);

    int m0 = blockIdx.x * 128;
    int n0 = blockIdx.y * 128;
    int t = threadIdx.x;
    int w = t >> 5;
    int lane = t & 31;
    int gid = lane >> 2;
    int tid4 = lane & 3;
    int wm = w >> 2;
    int wn = w & 3;

    auto load_chunk = [&](int c, int s) {
        int k0 = c * 64;
        uint32_t* sA = sm32 + s * G_STAGE_W;
        uint32_t* sB = sA + 128 * GW;
        #pragma unroll
        for (int it = 0; it < 4; it++) {
            int idx = it * 256 + t;
            int r = idx >> 3, c8 = idx & 7;
            uint32_t da = (uint32_t)__cvta_generic_to_shared(&sA[r * GW + c8 * 4]);
            CP_ASYNC16(da, (const char*)(Xh + (size_t)(m0 + r) * DMODEL + k0) + c8 * 16);
            uint32_t db = (uint32_t)__cvta_generic_to_shared(&sB[r * GW + c8 * 4]);
            CP_ASYNC16(db, (const char*)(Wth + (size_t)(n0 + r) * DMODEL + k0) + c8 * 16);
        }
        CP_COMMIT();
    };

    float acc[4][4][4];
    #pragma unroll
    for (int mt = 0; mt < 4; mt++)
        #pragma unroll
        for (int nt = 0; nt < 4; nt++)
            #pragma unroll
            for (int f = 0; f < 4; f++) acc[mt][nt][f] = 0.f;

    load_chunk(0, 0);
    load_chunk(1, 1);
    CP_WAIT1();
    __syncthreads();

    for (int c = 0; c < 12; c++) {
        int s = c & 1;
        const uint32_t* sA = sm32 + s * G_STAGE_W;
        const uint32_t* sB = sA + 128 * GW;
        #pragma unroll
        for (int ks = 0; ks < 4; ks++) {
            int o = ks * 8;
            uint32_t afr[4][4];
            #pragma unroll
            for (int mt = 0; mt < 4; mt++) {
                int r = wm * 64 + mt * 16 + gid;
                afr[mt][0] = sA[r * GW + tid4 + o];
                afr[mt][1] = sA[(r + 8) * GW + tid4 + o];
                afr[mt][2] = sA[r * GW + tid4 + 4 + o];
                afr[mt][3] = sA[(r + 8) * GW + tid4 + 4 + o];
            }
            #pragma unroll
            for (int nt = 0; nt < 4; nt++) {
                int n = wn * 32 + nt * 8 + gid;
                uint32_t bfr[2];
                bfr[0] = sB[n * GW + tid4 + o];
                bfr[1] = sB[n * GW + tid4 + 4 + o];
                #pragma unroll
                for (int mt = 0; mt < 4; mt++)
                    MMA_F16(acc[mt][nt], afr[mt], bfr);
            }
        }
        __syncthreads();
        if (c + 2 < 12) {
            load_chunk(c + 2, s);
            CP_WAIT1();
        } else {
            CP_WAIT0();
        }
        __syncthreads();
    }

    float bv2[4][2];
    #pragma unroll
    for (int nt = 0; nt < 4; nt++) {
        int col = n0 + wn * 32 + nt * 8 + tid4 * 2;
        bv2[nt][0] = bias[col];
        bv2[nt][1] = bias[col + 1];
    }
    #pragma unroll
    for (int mt = 0; mt < 4; mt++) {
        #pragma unroll
        for (int hf = 0; hf < 2; hf++) {
            int row = m0 + wm * 64 + mt * 16 + gid + hf * 8;
            int b = row >> 9, tok = row & 511;
            #pragma unroll
            for (int nt = 0; nt < 4; nt++) {
                int col = n0 + wn * 32 + nt * 8 + tid4 * 2;
                int head = col >> 6, dh = col & 63;
                float vx = acc[mt][nt][hf * 2 + 0] + bv2[nt][0];
                float vy = acc[mt][nt][hf * 2 + 1] + bv2[nt][1];
                if (sel == 2) {
                    size_t base = ((size_t)(b * HNUM + head) * 64 + dh) * 512 + tok;
                    g_Vth[base]       = __float2half_rn(vx);
                    g_Vth[base + 512] = __float2half_rn(vy);
                } else {
                    __half* Out = (sel == 0) ? g_Qh : g_Kh;
                    *(__half2*)&Out[((size_t)(b * HNUM + head) * 512 + tok) * 64 + dh] =
                        __floats2half2_rn(vx, vy);
                }
            }
        }
    }
}

// ---------------- K2b: qdp[row][r] = Q[row] . lnk[r] -------------------------
__global__ __launch_bounds__(256) void qdp_kernel() {
    int w = blockIdx.x * 8 + (threadIdx.x >> 5);
    int lane = threadIdx.x & 31;
    const __half* Qrow = g_Qh + (size_t)w * 64;
    float q0v = __half2float(Qrow[lane]), q1v = __half2float(Qrow[lane + 32]);
    float s0 = q0v * g_lnk[lane]       + q1v * g_lnk[lane + 32];
    float s1 = q0v * g_lnk[64 + lane]  + q1v * g_lnk[96 + lane];
    float s2 = q0v * g_lnk[128 + lane] + q1v * g_lnk[160 + lane];
    #pragma unroll
    for (int o = 16; o; o >>= 1) {
        s0 += __shfl_xor_sync(0xffffffffu, s0, o);
        s1 += __shfl_xor_sync(0xffffffffu, s1, o);
        s2 += __shfl_xor_sync(0xffffffffu, s2, o);
    }
    if (lane == 0)
        *(float4*)&g_QDP[w * 4] = make_float4(s0, s1, s2, 0.f);
}

// ---------------- KA: E = exp(QK^T/8 + qdp[arc] + mask) f32 + fused sums -----
#define QKW 36
#define QK_F32_OFF (2 * 128 * QKW)
#define QK_SMEM_BYTES ((QK_F32_OFF + 128 + 512) * 4 + 16384)

__global__ __launch_bounds__(256, 2) void qk_kernel(const float* __restrict__ mask) {
    extern __shared__ uint32_t sm32[];
    uint32_t* sQ = sm32;
    uint32_t* sK = sm32 + 128 * QKW;
    float* sMask = (float*)(sm32 + QK_F32_OFF);
    float* sQdp  = sMask + 128;
    unsigned char* sArc = (unsigned char*)(sQdp + 512);

    int bh = blockIdx.z;
    int b = bh / HNUM;
    int q0 = blockIdx.x * 128;
    int k0 = blockIdx.y * 128;
    int t = threadIdx.x;
    int w = t >> 5;
    int lane = t & 31;
    int gid = lane >> 2;
    int tid4 = lane & 3;
    int wm = w >> 2;
    int wn = w & 3;

    const __half* Qbase = g_Qh + ((size_t)bh * 512 + q0) * 64;
    const __half* Kbase = g_Kh + ((size_t)bh * 512 + k0) * 64;
    const char* Abase = (const char*)g_arc8 + ((size_t)(b * 512 + q0)) * 512 + k0;

    #pragma unroll
    for (int it = 0; it < 4; it++) {
        int idx = it * 256 + t;
        int r = idx >> 3, c = idx & 7;
        uint32_t dq = (uint32_t)__cvta_generic_to_shared(&sQ[r * QKW + c * 4]);
        CP_ASYNC16(dq, (const char*)(Qbase + (size_t)r * 64) + c * 16);
        uint32_t dk = (uint32_t)__cvta_generic_to_shared(&sK[r * QKW + c * 4]);
        CP_ASYNC16(dk, (const char*)(Kbase + (size_t)r * 64) + c * 16);
        uint32_t da = (uint32_t)__cvta_generic_to_shared(&sArc[r * 128 + c * 16]);
        CP_ASYNC16(da, Abase + (size_t)r * 512 + c * 16);
    }
    CP_COMMIT();
    if (t < 128) {
        sMask[t] = mask[b * 512 + k0 + t];
        *(float4*)&sQdp[t * 4] = *(const float4*)&g_QDP[((size_t)bh * 512 + q0 + t) * 4];
    }
    CP_WAIT0();
    __syncthreads();

    float acc[4][4][4];
    #pragma unroll
    for (int mt = 0; mt < 4; mt++)
        #pragma unroll
        for (int nt = 0; nt < 4; nt++)
            #pragma unroll
            for (int f = 0; f < 4; f++) acc[mt][nt][f] = 0.f;

    #pragma unroll
    for (int ks = 0; ks < 4; ks++) {
        int o = ks * 8;
        uint32_t afr[4][4];
        #pragma unroll
        for (int mt = 0; mt < 4; mt++) {
            int r = wm * 64 + mt * 16 + gid;
            afr[mt][0] = sQ[r * QKW + tid4 + o];
            afr[mt][1] = sQ[(r + 8) * QKW + tid4 + o];
            afr[mt][2] = sQ[r * QKW + tid4 + 4 + o];
            afr[mt][3] = sQ[(r + 8) * QKW + tid4 + 4 + o];
        }
        #pragma unroll
        for (int nt = 0; nt < 4; nt++) {
            int n = wn * 32 + nt * 8 + gid;
            uint32_t bfr[2];
            bfr[0] = sK[n * QKW + tid4 + o];
            bfr[1] = sK[n * QKW + tid4 + 4 + o];
            #pragma unroll
            for (int mt = 0; mt < 4; mt++)
                MMA_F16(acc[mt][nt], afr[mt], bfr);
        }
    }

    #pragma unroll
    for (int mt = 0; mt < 4; mt++) {
        #pragma unroll
        for (int hf = 0; hf < 2; hf++) {
            int rl = wm * 64 + mt * 16 + gid + hf * 8;
            float* Erow = g_S + ((size_t)bh * 512 + q0 + rl) * 512 + k0;
            float lsum = 0.f, lp1 = 0.f, lp2 = 0.f;
            #pragma unroll
            for (int nt = 0; nt < 4; nt++) {
                int lc = wn * 32 + nt * 8 + tid4 * 2;
                int a0 = sArc[rl * 128 + lc];
                int a1 = sArc[rl * 128 + lc + 1];
                float e0 = __expf(fmaf(acc[mt][nt][hf * 2 + 0], 0.125f,
                                       sQdp[rl * 4 + a0] + sMask[lc]));
                float e1 = __expf(fmaf(acc[mt][nt][hf * 2 + 1], 0.125f,
                                       sQdp[rl * 4 + a1] + sMask[lc + 1]));
                *(float2*)&Erow[lc] = make_float2(e0, e1);
                lsum += e0 + e1;
                lp1 += ((a0 == 1) ? e0 : 0.f) + ((a1 == 1) ? e1 : 0.f);
                lp2 += ((a0 == 2) ? e0 : 0.f) + ((a1 == 2) ? e1 : 0.f);
            }
            lsum += __shfl_xor_sync(0xffffffffu, lsum, 1);
            lsum += __shfl_xor_sync(0xffffffffu, lsum, 2);
            lp1  += __shfl_xor_sync(0xffffffffu, lp1, 1);
            lp1  += __shfl_xor_sync(0xffffffffu, lp1, 2);
            lp2  += __shfl_xor_sync(0xffffffffu, lp2, 1);
            lp2  += __shfl_xor_sync(0xffffffffu, lp2, 2);
            if (tid4 == 0) {
                float* dst = &g_SUM[((size_t)bh * 512 + q0 + rl) * 4];
                atomicAdd(dst + 0, lsum);
                atomicAdd(dst + 1, lp1);
                atomicAdd(dst + 2, lp2);
            }
        }
    }
}

// ---------------- KC: O = (E/sum) V + pw . lnv -------------------------------
// E loaded f32, normalized per-row during f32->half conversion (half-safe).
#define PVW 20
#define PV_STAGE_W (64 * PVW + 64 * PVW)
#define PV_SMEM_BYTES (2 * PV_STAGE_W * 4)

__global__ __launch_bounds__(256, 4) void pv_kernel(float* __restrict__ out) {
    extern __shared__ uint32_t sm32[];

    int bh = blockIdx.y;
    int b = bh / HNUM, h = bh % HNUM;
    int q0 = blockIdx.x * 64;
    int t = threadIdx.x;
    int w = t >> 5;
    int lane = t & 31;
    int gid = lane >> 2;
    int tid4 = lane & 3;
    int wm = w >> 1;
    int wn = w & 1;

    const float* Ebase = g_S + ((size_t)bh * 512 + q0) * 512;
    const __half* Vtbase = g_Vth + (size_t)bh * 64 * 512;

    // E-load mapping: this thread always handles local row er, cols ec..ec+7
    int er = t >> 2;
    int ec = (t & 3) * 8;
    float inv_e = 1.f / g_SUM[((size_t)bh * 512 + q0 + er) * 4];

    float4 eA, eB;
    auto loadE = [&](int c) {
        const float* p = Ebase + (size_t)er * 512 + c * 32 + ec;
        eA = *(const float4*)p;
        eB = *(const float4*)(p + 4);
    };
    auto storeE = [&](uint32_t* buf) {
        uint32_t* sP = buf;
        uint4 v;
        v.x = h2_bits(__floats2half2_rn(eA.x * inv_e, eA.y * inv_e));
        v.y = h2_bits(__floats2half2_rn(eA.z * inv_e, eA.w * inv_e));
        v.z = h2_bits(__floats2half2_rn(eB.x * inv_e, eB.y * inv_e));
        v.w = h2_bits(__floats2half2_rn(eB.z * inv_e, eB.w * inv_e));
        *(uint4*)&sP[er * PVW + (t & 3) * 4] = v;
    };
    auto loadV = [&](int c, uint32_t* buf) {
        int k0 = c * 32;
        uint32_t* sV = buf + 64 * PVW;
        int r = t >> 2, c4 = t & 3;
        uint32_t dv = (uint32_t)__cvta_generic_to_shared(&sV[r * PVW + c4 * 4]);
        CP_ASYNC16(dv, (const char*)(Vtbase + (size_t)r * 512 + k0) + c4 * 16);
        CP_COMMIT();
    };

    uint32_t* buf0 = sm32;
    uint32_t* buf1 = sm32 + PV_STAGE_W;

    float acc[4][4];
    #pragma unroll
    for (int nt = 0; nt < 4; nt++)
        #pragma unroll
        for (int f = 0; f < 4; f++) acc[nt][f] = 0.f;

    loadE(0);
    storeE(buf0);
    loadV(0, buf0);
    loadV(1, buf1);
    loadE(1);
    CP_WAIT1();          // V(0) complete
    __syncthreads();

    for (int c = 0; c < 16; c++) {
        uint32_t* bufc = (c & 1) ? buf1 : buf0;
        uint32_t* bufn = (c & 1) ? buf0 : buf1;
        const uint32_t* sP = bufc;
        const uint32_t* sV = bufc + 64 * PVW;
        #pragma unroll
        for (int ks = 0; ks < 2; ks++) {
            int o = ks * 8;
            uint32_t afr[4];
            int r = wm * 16 + gid;
            afr[0] = sP[r * PVW + tid4 + o];
            afr[1] = sP[(r + 8) * PVW + tid4 + o];
            afr[2] = sP[r * PVW + tid4 + 4 + o];
            afr[3] = sP[(r + 8) * PVW + tid4 + 4 + o];
            #pragma unroll
            for (int nt = 0; nt < 4; nt++) {
                int n = wn * 32 + nt * 8 + gid;
                uint32_t bfr[2];
                bfr[0] = sV[n * PVW + tid4 + o];
                bfr[1] = sV[n * PVW + tid4 + 4 + o];
                MMA_F16(acc[nt], afr, bfr);
            }
        }
        __syncthreads();              // all warps done reading bufc (and bufn from prev iter)
        if (c + 1 < 16) {
            storeE(bufn);             // E(c+1) regs -> next buffer
            if (c + 2 < 16) {
                loadE(c + 2);
                loadV(c + 2, bufc);   // bufc free after the sync above
                CP_WAIT1();           // V(c+1) complete
            } else {
                CP_WAIT0();
            }
            __syncthreads();          // bufn {E(c+1), V(c+1)} visible
        }
    }

    int r0 = wm * 16 + gid, r1 = r0 + 8;
    float4 s0v = *(float4*)&g_SUM[((size_t)bh * 512 + q0 + r0) * 4];
    float4 s1v = *(float4*)&g_SUM[((size_t)bh * 512 + q0 + r1) * 4];
    float inv0 = 1.f / s0v.x, inv1 = 1.f / s1v.x;
    float p01 = s0v.y * inv0, p02 = s0v.z * inv0, p00 = 1.f - p01 - p02;
    float p11 = s1v.y * inv1, p12 = s1v.z * inv1, p10 = 1.f - p11 - p12;
    #pragma unroll
    for (int nt = 0; nt < 4; nt++) {
        int col = wn * 32 + nt * 8 + tid4 * 2;
        float l0a = g_lnv[col],       l0b = g_lnv[col + 1];
        float l1a = g_lnv[64 + col],  l1b = g_lnv[64 + col + 1];
        float l2a = g_lnv[128 + col], l2b = g_lnv[128 + col + 1];
        float2 v0, v1;
        v0.x = acc[nt][0] + p00 * l0a + p01 * l1a + p02 * l2a;
        v0.y = acc[nt][1] + p00 * l0b + p01 * l1b + p02 * l2b;
        v1.x = acc[nt][2] + p10 * l0a + p11 * l1a + p12 * l2a;
        v1.y = acc[nt][3] + p10 * l0b + p11 * l1b + p12 * l2b;
        *(float2*)&out[(size_t)(b * 512 + q0 + r0) * 768 + h * 64 + col] = v0;
        *(float2*)&out[(size_t)(b * 512 + q0 + r1) * 768 + h * 64 + col] = v1;
    }
}

// ---------------- launcher ----------------------------------------------------
extern "C" void kernel_launch(void* const* d_in, const int* in_sizes, int n_in,
                              void* d_out, int out_size) {
    const float* hidden = (const float*)d_in[0];
    const float* ctx    = (const float*)d_in[1];
    const float* mask   = (const float*)d_in[2];
    const int*   arc    = (const int*)d_in[3];
    const float* Wq = (const float*)d_in[4];  const float* bq = (const float*)d_in[5];
    const float* Wk = (const float*)d_in[6];  const float* bk = (const float*)d_in[7];
    const float* Wv = (const float*)d_in[8];  const float* bv = (const float*)d_in[9];
    const float* dpk = (const float*)d_in[10]; const float* dpv = (const float*)d_in[11];
    const float* lkg = (const float*)d_in[12]; const float* lkb = (const float*)d_in[13];
    const float* lvg = (const float*)d_in[14]; const float* lvb = (const float*)d_in[15];
    float* out = (float*)d_out;

    prep_kernel<<<5921, 256>>>(arc, hidden, ctx, Wq, Wk, Wv,
                               dpk, dpv, lkg, lkb, lvg, lvb);

    cudaFuncSetAttribute(qkv_gemm_f16_kernel, cudaFuncAttributeMaxDynamicSharedMemorySize,
                         GEMM_SMEM_BYTES);
    qkv_gemm_f16_kernel<<<dim3(16, 6, 3), 256, GEMM_SMEM_BYTES>>>(bq, bk, bv);

    qdp_kernel<<<3072, 256>>>();

    cudaFuncSetAttribute(qk_kernel, cudaFuncAttributeMaxDynamicSharedMemorySize,
                         QK_SMEM_BYTES);
    qk_kernel<<<dim3(4, 4, 48), 256, QK_SMEM_BYTES>>>(mask);

    cudaFuncSetAttribute(pv_kernel, cudaFuncAttributeMaxDynamicSharedMemorySize,
                         PV_SMEM_BYTES);
    pv_kernel<<<dim3(8, 48), 256, PV_SMEM_BYTES>>>(out);
}

// round 15
// speedup vs baseline: 1.1188x; 1.0245x over previous
#include <cuda_runtime.h>
#include <cuda_fp16.h>
#include <cstdint>

#define HNUM 12
#define DHEAD 64
#define BATCH 4
#define LQ 512
#define LK 512
#define DMODEL 768
#define XSIZE (BATCH*LQ*DMODEL)
#define NROWS (BATCH*HNUM*LQ)

// ---------------- scratch (device globals; no runtime alloc) ----------------
__device__ __half g_Xh[2*XSIZE];
__device__ __half g_Wth[3][DMODEL*DMODEL];
__device__ __half g_Qh[BATCH*HNUM*LQ*DHEAD];
__device__ __half g_Kh[BATCH*HNUM*LK*DHEAD];
__device__ __half g_Vth[(size_t)BATCH*HNUM*DHEAD*LK];
__device__ float  g_S[(size_t)BATCH*HNUM*LQ*LK];
__device__ float  g_SUM[NROWS*4];
__device__ float  g_QDP[NROWS*4];
__device__ uint32_t g_arc8[BATCH*512*512/4];
__device__ float  g_lnk[3*DHEAD];
__device__ float  g_lnv[3*DHEAD];

__device__ __forceinline__ uint32_t h2_bits(__half2 h) {
    union { __half2 h; uint32_t u; } cvt;
    cvt.h = h;
    return cvt.u;
}

#define MMA_F16(d, a, b)                                                      \
    asm volatile("mma.sync.aligned.m16n8k16.row.col.f32.f16.f16.f32 "          \
        "{%0,%1,%2,%3}, {%4,%5,%6,%7}, {%8,%9}, {%0,%1,%2,%3};"                \
        : "+f"((d)[0]), "+f"((d)[1]), "+f"((d)[2]), "+f"((d)[3])               \
        : "r"((a)[0]), "r"((a)[1]), "r"((a)[2]), "r"((a)[3]),                  \
          "r"((b)[0]), "r"((b)[1]))

#define LDSM_X4(r, addr)                                                      \
    asm volatile("ldmatrix.sync.aligned.m8n8.x4.shared.b16 {%0,%1,%2,%3}, [%4];" \
        : "=r"((r)[0]), "=r"((r)[1]), "=r"((r)[2]), "=r"((r)[3]) : "r"(addr))

#define CP_ASYNC16(dst, src) \
    asm volatile("cp.async.cg.shared.global [%0], [%1], 16;" :: "r"(dst), "l"(src) : "memory")
#define CP_COMMIT() asm volatile("cp.async.commit_group;" ::: "memory")
#define CP_WAIT1()  asm volatile("cp.async.wait_group 1;" ::: "memory")
#define CP_WAIT0()  asm volatile("cp.async.wait_group 0;" ::: "memory")

// ---------------- K1: arc pack | X cvt | W transpose | zero sums | LN --------
__global__ __launch_bounds__(256) void prep_kernel(
    const int* __restrict__ arc,
    const float* __restrict__ hidden, const float* __restrict__ ctx,
    const float* __restrict__ Wq, const float* __restrict__ Wk,
    const float* __restrict__ Wv,
    const float* __restrict__ dpk, const float* __restrict__ dpv,
    const float* __restrict__ kg, const float* __restrict__ kb,
    const float* __restrict__ vg, const float* __restrict__ vb) {
    int bx = blockIdx.x;
    int t = threadIdx.x;
    if (bx < 1024) {
        int i = bx * 256 + t;
        const int4 a = *(const int4*)&arc[i * 4];
        g_arc8[i] = (uint32_t)a.x | ((uint32_t)a.y << 8) |
                    ((uint32_t)a.z << 16) | ((uint32_t)a.w << 24);
        return;
    }
    if (bx < 4096) {
        bool is_h = bx < 2560;
        const float* src = is_h ? hidden : ctx;
        __half* dst = g_Xh + (is_h ? 0 : XSIZE);
        int i = ((bx - (is_h ? 1024 : 2560)) * 256 + t) * 4;
        float4 v = *(const float4*)&src[i];
        *(__half2*)&dst[i]     = __floats2half2_rn(v.x, v.y);
        *(__half2*)&dst[i + 2] = __floats2half2_rn(v.z, v.w);
        return;
    }
    if (bx < 5824) {
        __shared__ float tile[32][33];
        int wb = bx - 4096;
        int sel = wb / 576;
        int tl = wb % 576;
        int tx0 = (tl % 24) * 32, ty0 = (tl / 24) * 32;
        const float* W = (sel == 0) ? Wq : (sel == 1 ? Wk : Wv);
        __half* WT = g_Wth[sel];
        int tx = t & 31, ty = t >> 5;
        #pragma unroll
        for (int i = 0; i < 32; i += 8)
            tile[ty + i][tx] = W[(size_t)(ty0 + ty + i) * DMODEL + tx0 + tx];
        __syncthreads();
        #pragma unroll
        for (int i = 0; i < 32; i += 8)
            WT[(size_t)(tx0 + ty + i) * DMODEL + ty0 + tx] =
                __float2half_rn(tile[tx][ty + i]);
        return;
    }
    if (bx < 5920) {
        int i = (bx - 5824) * 256 + t;
        *(float4*)&g_SUM[i * 4] = make_float4(0.f, 0.f, 0.f, 0.f);
        return;
    }
    int w = t >> 5;
    int lane = t & 31;
    if (w >= 6) return;
    const float* src = (w < 3) ? dpk + w * DHEAD : dpv + (w - 3) * DHEAD;
    const float* g   = (w < 3) ? kg : vg;
    const float* be  = (w < 3) ? kb : vb;
    float* dst       = (w < 3) ? g_lnk + w * DHEAD : g_lnv + (w - 3) * DHEAD;
    float e0 = src[lane], e1 = src[lane + 32];
    float s = e0 + e1;
    #pragma unroll
    for (int o = 16; o; o >>= 1) s += __shfl_xor_sync(0xffffffffu, s, o);
    float mu = s * (1.0f / 64.0f);
    float d0 = e0 - mu, d1 = e1 - mu;
    float v = d0 * d0 + d1 * d1;
    #pragma unroll
    for (int o = 16; o; o >>= 1) v += __shfl_xor_sync(0xffffffffu, v, o);
    float rs = rsqrtf(v * (1.0f / 64.0f) + 1e-5f);
    dst[lane]      = d0 * rs * g[lane]      + be[lane];
    dst[lane + 32] = d1 * rs * g[lane + 32] + be[lane + 32];
}

// ---------------- K2: f16 mma.sync QKV GEMM (ldmatrix) -----------------------
#define GW 36
#define G_STAGE_W (128 * GW * 2)
#define GEMM_SMEM_BYTES (2 * G_STAGE_W * 4)

__global__ __launch_bounds__(256, 2) void qkv_gemm_f16_kernel(
    const float* __restrict__ bq, const float* __restrict__ bk,
    const float* __restrict__ bv) {
    extern __shared__ uint32_t sm32[];

    int sel = blockIdx.z;
    const __half* Xh = g_Xh + ((sel == 0) ? 0 : XSIZE);
    const __half* Wth = g_Wth[sel];
    const float* bias = (sel == 0) ? bq : (sel == 1 ? bk : bv);

    int m0 = blockIdx.x * 128;
    int n0 = blockIdx.y * 128;
    int t = threadIdx.x;
    int w = t >> 5;
    int lane = t & 31;
    int gid = lane >> 2;
    int tid4 = lane & 3;
    int wm = w >> 2;
    int wn = w & 3;

    auto load_chunk = [&](int c, int s) {
        int k0 = c * 64;
        uint32_t* sA = sm32 + s * G_STAGE_W;
        uint32_t* sB = sA + 128 * GW;
        #pragma unroll
        for (int it = 0; it < 4; it++) {
            int idx = it * 256 + t;
            int r = idx >> 3, c8 = idx & 7;
            uint32_t da = (uint32_t)__cvta_generic_to_shared(&sA[r * GW + c8 * 4]);
            CP_ASYNC16(da, (const char*)(Xh + (size_t)(m0 + r) * DMODEL + k0) + c8 * 16);
            uint32_t db = (uint32_t)__cvta_generic_to_shared(&sB[r * GW + c8 * 4]);
            CP_ASYNC16(db, (const char*)(Wth + (size_t)(n0 + r) * DMODEL + k0) + c8 * 16);
        }
        CP_COMMIT();
    };

    // ldmatrix base addresses (bytes into smem)
    uint32_t sbase = (uint32_t)__cvta_generic_to_shared(sm32);
    int rA = wm * 64 + (lane & 7) + ((lane >> 3) & 1) * 8;
    int wA = (lane >> 4) * 4;
    uint32_t addrA = sbase + (uint32_t)(rA * GW + wA) * 4;
    int rB = wn * 32 + (lane >> 4) * 8 + (lane & 7);
    int wB = ((lane >> 3) & 1) * 4;
    uint32_t addrB = sbase + (uint32_t)(128 * GW + rB * GW + wB) * 4;

    float acc[4][4][4];
    #pragma unroll
    for (int mt = 0; mt < 4; mt++)
        #pragma unroll
        for (int nt = 0; nt < 4; nt++)
            #pragma unroll
            for (int f = 0; f < 4; f++) acc[mt][nt][f] = 0.f;

    load_chunk(0, 0);
    load_chunk(1, 1);
    CP_WAIT1();
    __syncthreads();

    for (int c = 0; c < 12; c++) {
        int s = c & 1;
        uint32_t stOff = (uint32_t)(s * G_STAGE_W) * 4;
        #pragma unroll
        for (int ks = 0; ks < 4; ks++) {
            uint32_t kOff = stOff + ks * 32;
            uint32_t afr[4][4];
            #pragma unroll
            for (int mt = 0; mt < 4; mt++)
                LDSM_X4(afr[mt], addrA + kOff + (uint32_t)(mt * 16 * GW) * 4);
            uint32_t bw[8];
            LDSM_X4(bw,     addrB + kOff);
            LDSM_X4(bw + 4, addrB + kOff + (uint32_t)(16 * GW) * 4);
            #pragma unroll
            for (int nt = 0; nt < 4; nt++)
                #pragma unroll
                for (int mt = 0; mt < 4; mt++)
                    MMA_F16(acc[mt][nt], afr[mt], &bw[nt * 2]);
        }
        __syncthreads();
        if (c + 2 < 12) {
            load_chunk(c + 2, s);
            CP_WAIT1();
        } else {
            CP_WAIT0();
        }
        __syncthreads();
    }

    float bv2[4][2];
    #pragma unroll
    for (int nt = 0; nt < 4; nt++) {
        int col = n0 + wn * 32 + nt * 8 + tid4 * 2;
        bv2[nt][0] = bias[col];
        bv2[nt][1] = bias[col + 1];
    }
    #pragma unroll
    for (int mt = 0; mt < 4; mt++) {
        #pragma unroll
        for (int hf = 0; hf < 2; hf++) {
            int row = m0 + wm * 64 + mt * 16 + gid + hf * 8;
            int b = row >> 9, tok = row & 511;
            #pragma unroll
            for (int nt = 0; nt < 4; nt++) {
                int col = n0 + wn * 32 + nt * 8 + tid4 * 2;
                int head = col >> 6, dh = col & 63;
                float vx = acc[mt][nt][hf * 2 + 0] + bv2[nt][0];
                float vy = acc[mt][nt][hf * 2 + 1] + bv2[nt][1];
                if (sel == 2) {
                    size_t base = ((size_t)(b * HNUM + head) * 64 + dh) * 512 + tok;
                    g_Vth[base]       = __float2half_rn(vx);
                    g_Vth[base + 512] = __float2half_rn(vy);
                } else {
                    __half* Out = (sel == 0) ? g_Qh : g_Kh;
                    *(__half2*)&Out[((size_t)(b * HNUM + head) * 512 + tok) * 64 + dh] =
                        __floats2half2_rn(vx, vy);
                }
            }
        }
    }
}

// ---------------- K2b: qdp[row][r] = Q[row] . lnk[r] -------------------------
__global__ __launch_bounds__(256) void qdp_kernel() {
    int w = blockIdx.x * 8 + (threadIdx.x >> 5);
    int lane = threadIdx.x & 31;
    const __half* Qrow = g_Qh + (size_t)w * 64;
    float q0v = __half2float(Qrow[lane]), q1v = __half2float(Qrow[lane + 32]);
    float s0 = q0v * g_lnk[lane]       + q1v * g_lnk[lane + 32];
    float s1 = q0v * g_lnk[64 + lane]  + q1v * g_lnk[96 + lane];
    float s2 = q0v * g_lnk[128 + lane] + q1v * g_lnk[160 + lane];
    #pragma unroll
    for (int o = 16; o; o >>= 1) {
        s0 += __shfl_xor_sync(0xffffffffu, s0, o);
        s1 += __shfl_xor_sync(0xffffffffu, s1, o);
        s2 += __shfl_xor_sync(0xffffffffu, s2, o);
    }
    if (lane == 0)
        *(float4*)&g_QDP[w * 4] = make_float4(s0, s1, s2, 0.f);
}

// ---------------- KA: E = exp(QK^T/8 + qdp[arc] + mask) f32 + fused sums -----
#define QKW 36
#define QK_F32_OFF (2 * 128 * QKW)
#define QK_SMEM_BYTES ((QK_F32_OFF + 128 + 512) * 4 + 16384)

__global__ __launch_bounds__(256, 2) void qk_kernel(const float* __restrict__ mask) {
    extern __shared__ uint32_t sm32[];
    uint32_t* sQ = sm32;
    uint32_t* sK = sm32 + 128 * QKW;
    float* sMask = (float*)(sm32 + QK_F32_OFF);
    float* sQdp  = sMask + 128;
    unsigned char* sArc = (unsigned char*)(sQdp + 512);

    int bh = blockIdx.z;
    int b = bh / HNUM;
    int q0 = blockIdx.x * 128;
    int k0 = blockIdx.y * 128;
    int t = threadIdx.x;
    int w = t >> 5;
    int lane = t & 31;
    int gid = lane >> 2;
    int tid4 = lane & 3;
    int wm = w >> 2;
    int wn = w & 3;

    const __half* Qbase = g_Qh + ((size_t)bh * 512 + q0) * 64;
    const __half* Kbase = g_Kh + ((size_t)bh * 512 + k0) * 64;
    const char* Abase = (const char*)g_arc8 + ((size_t)(b * 512 + q0)) * 512 + k0;

    #pragma unroll
    for (int it = 0; it < 4; it++) {
        int idx = it * 256 + t;
        int r = idx >> 3, c = idx & 7;
        uint32_t dq = (uint32_t)__cvta_generic_to_shared(&sQ[r * QKW + c * 4]);
        CP_ASYNC16(dq, (const char*)(Qbase + (size_t)r * 64) + c * 16);
        uint32_t dk = (uint32_t)__cvta_generic_to_shared(&sK[r * QKW + c * 4]);
        CP_ASYNC16(dk, (const char*)(Kbase + (size_t)r * 64) + c * 16);
        uint32_t da = (uint32_t)__cvta_generic_to_shared(&sArc[r * 128 + c * 16]);
        CP_ASYNC16(da, Abase + (size_t)r * 512 + c * 16);
    }
    CP_COMMIT();
    if (t < 128) {
        sMask[t] = mask[b * 512 + k0 + t];
        *(float4*)&sQdp[t * 4] = *(const float4*)&g_QDP[((size_t)bh * 512 + q0 + t) * 4];
    }
    CP_WAIT0();
    __syncthreads();

    uint32_t sbase = (uint32_t)__cvta_generic_to_shared(sm32);
    int rA = wm * 64 + (lane & 7) + ((lane >> 3) & 1) * 8;
    int wA = (lane >> 4) * 4;
    uint32_t addrA = sbase + (uint32_t)(rA * QKW + wA) * 4;
    int rB = wn * 32 + (lane >> 4) * 8 + (lane & 7);
    int wB = ((lane >> 3) & 1) * 4;
    uint32_t addrB = sbase + (uint32_t)(128 * QKW + rB * QKW + wB) * 4;

    float acc[4][4][4];
    #pragma unroll
    for (int mt = 0; mt < 4; mt++)
        #pragma unroll
        for (int nt = 0; nt < 4; nt++)
            #pragma unroll
            for (int f = 0; f < 4; f++) acc[mt][nt][f] = 0.f;

    #pragma unroll
    for (int ks = 0; ks < 4; ks++) {
        uint32_t kOff = ks * 32;
        uint32_t afr[4][4];
        #pragma unroll
        for (int mt = 0; mt < 4; mt++)
            LDSM_X4(afr[mt], addrA + kOff + (uint32_t)(mt * 16 * QKW) * 4);
        uint32_t bw[8];
        LDSM_X4(bw,     addrB + kOff);
        LDSM_X4(bw + 4, addrB + kOff + (uint32_t)(16 * QKW) * 4);
        #pragma unroll
        for (int nt = 0; nt < 4; nt++)
            #pragma unroll
            for (int mt = 0; mt < 4; mt++)
                MMA_F16(acc[mt][nt], afr[mt], &bw[nt * 2]);
    }

    #pragma unroll
    for (int mt = 0; mt < 4; mt++) {
        #pragma unroll
        for (int hf = 0; hf < 2; hf++) {
            int rl = wm * 64 + mt * 16 + gid + hf * 8;
            float* Erow = g_S + ((size_t)bh * 512 + q0 + rl) * 512 + k0;
            float lsum = 0.f, lp1 = 0.f, lp2 = 0.f;
            #pragma unroll
            for (int nt = 0; nt < 4; nt++) {
                int lc = wn * 32 + nt * 8 + tid4 * 2;
                int a0 = sArc[rl * 128 + lc];
                int a1 = sArc[rl * 128 + lc + 1];
                float e0 = __expf(fmaf(acc[mt][nt][hf * 2 + 0], 0.125f,
                                       sQdp[rl * 4 + a0] + sMask[lc]));
                float e1 = __expf(fmaf(acc[mt][nt][hf * 2 + 1], 0.125f,
                                       sQdp[rl * 4 + a1] + sMask[lc + 1]));
                *(float2*)&Erow[lc] = make_float2(e0, e1);
                lsum += e0 + e1;
                lp1 += ((a0 == 1) ? e0 : 0.f) + ((a1 == 1) ? e1 : 0.f);
                lp2 += ((a0 == 2) ? e0 : 0.f) + ((a1 == 2) ? e1 : 0.f);
            }
            lsum += __shfl_xor_sync(0xffffffffu, lsum, 1);
            lsum += __shfl_xor_sync(0xffffffffu, lsum, 2);
            lp1  += __shfl_xor_sync(0xffffffffu, lp1, 1);
            lp1  += __shfl_xor_sync(0xffffffffu, lp1, 2);
            lp2  += __shfl_xor_sync(0xffffffffu, lp2, 1);
            lp2  += __shfl_xor_sync(0xffffffffu, lp2, 2);
            if (tid4 == 0) {
                float* dst = &g_SUM[((size_t)bh * 512 + q0 + rl) * 4];
                atomicAdd(dst + 0, lsum);
                atomicAdd(dst + 1, lp1);
                atomicAdd(dst + 2, lp2);
            }
        }
    }
}

// ---------------- KC: O = (E/sum) V + pw . lnv (ldmatrix) --------------------
#define PVW 20
#define PV_STAGE_W (64 * PVW + 64 * PVW)
#define PV_SMEM_BYTES (2 * PV_STAGE_W * 4)

__global__ __launch_bounds__(256, 4) void pv_kernel(float* __restrict__ out) {
    extern __shared__ uint32_t sm32[];

    int bh = blockIdx.y;
    int b = bh / HNUM, h = bh % HNUM;
    int q0 = blockIdx.x * 64;
    int t = threadIdx.x;
    int w = t >> 5;
    int lane = t & 31;
    int gid = lane >> 2;
    int tid4 = lane & 3;
    int wm = w >> 1;
    int wn = w & 1;

    const float* Ebase = g_S + ((size_t)bh * 512 + q0) * 512;
    const __half* Vtbase = g_Vth + (size_t)bh * 64 * 512;

    int er = t >> 2;
    int ec = (t & 3) * 8;
    float inv_e = 1.f / g_SUM[((size_t)bh * 512 + q0 + er) * 4];

    float4 eA, eB;
    auto loadE = [&](int c) {
        const float* p = Ebase + (size_t)er * 512 + c * 32 + ec;
        eA = *(const float4*)p;
        eB = *(const float4*)(p + 4);
    };
    auto storeE = [&](uint32_t* buf) {
        uint4 v;
        v.x = h2_bits(__floats2half2_rn(eA.x * inv_e, eA.y * inv_e));
        v.y = h2_bits(__floats2half2_rn(eA.z * inv_e, eA.w * inv_e));
        v.z = h2_bits(__floats2half2_rn(eB.x * inv_e, eB.y * inv_e));
        v.w = h2_bits(__floats2half2_rn(eB.z * inv_e, eB.w * inv_e));
        *(uint4*)&buf[er * PVW + (t & 3) * 4] = v;
    };
    auto loadV = [&](int c, uint32_t* buf) {
        int k0 = c * 32;
        uint32_t* sV = buf + 64 * PVW;
        int r = t >> 2, c4 = t & 3;
        uint32_t dv = (uint32_t)__cvta_generic_to_shared(&sV[r * PVW + c4 * 4]);
        CP_ASYNC16(dv, (const char*)(Vtbase + (size_t)r * 512 + k0) + c4 * 16);
        CP_COMMIT();
    };

    uint32_t* buf0 = sm32;
    uint32_t* buf1 = sm32 + PV_STAGE_W;

    uint32_t sbase = (uint32_t)__cvta_generic_to_shared(sm32);
    int rA = wm * 16 + (lane & 7) + ((lane >> 3) & 1) * 8;
    int wA = (lane >> 4) * 4;
    uint32_t addrA = sbase + (uint32_t)(rA * PVW + wA) * 4;
    int rB = wn * 32 + (lane >> 4) * 8 + (lane & 7);
    int wB = ((lane >> 3) & 1) * 4;
    uint32_t addrB = sbase + (uint32_t)(64 * PVW + rB * PVW + wB) * 4;

    float acc[4][4];
    #pragma unroll
    for (int nt = 0; nt < 4; nt++)
        #pragma unroll
        for (int f = 0; f < 4; f++) acc[nt][f] = 0.f;

    loadE(0);
    storeE(buf0);
    loadV(0, buf0);
    loadV(1, buf1);
    loadE(1);
    CP_WAIT1();
    __syncthreads();

    for (int c = 0; c < 16; c++) {
        uint32_t* bufc = (c & 1) ? buf1 : buf0;
        uint32_t* bufn = (c & 1) ? buf0 : buf1;
        uint32_t bOff = (uint32_t)((c & 1) ? PV_STAGE_W * 4 : 0);
        #pragma unroll
        for (int ks = 0; ks < 2; ks++) {
            uint32_t kOff = bOff + ks * 32;
            uint32_t afr[4];
            LDSM_X4(afr, addrA + kOff);
            uint32_t bw[8];
            LDSM_X4(bw,     addrB + kOff);
            LDSM_X4(bw + 4, addrB + kOff + (uint32_t)(16 * PVW) * 4);
            #pragma unroll
            for (int nt = 0; nt < 4; nt++)
                MMA_F16(acc[nt], afr, &bw[nt * 2]);
        }
        __syncthreads();
        if (c + 1 < 16) {
            storeE(bufn);
            if (c + 2 < 16) {
                loadE(c + 2);
                loadV(c + 2, bufc);
                CP_WAIT1();
            } else {
                CP_WAIT0();
            }
            __syncthreads();
        }
    }

    int r0 = wm * 16 + gid, r1 = r0 + 8;
    float4 s0v = *(float4*)&g_SUM[((size_t)bh * 512 + q0 + r0) * 4];
    float4 s1v = *(float4*)&g_SUM[((size_t)bh * 512 + q0 + r1) * 4];
    float inv0 = 1.f / s0v.x, inv1 = 1.f / s1v.x;
    float p01 = s0v.y * inv0, p02 = s0v.z * inv0, p00 = 1.f - p01 - p02;
    float p11 = s1v.y * inv1, p12 = s1v.z * inv1, p10 = 1.f - p11 - p12;
    #pragma unroll
    for (int nt = 0; nt < 4; nt++) {
        int col = wn * 32 + nt * 8 + tid4 * 2;
        float l0a = g_lnv[col],       l0b = g_lnv[col + 1];
        float l1a = g_lnv[64 + col],  l1b = g_lnv[64 + col + 1];
        float l2a = g_lnv[128 + col], l2b = g_lnv[128 + col + 1];
        float2 v0, v1;
        v0.x = acc[nt][0] + p00 * l0a + p01 * l1a + p02 * l2a;
        v0.y = acc[nt][1] + p00 * l0b + p01 * l1b + p02 * l2b;
        v1.x = acc[nt][2] + p10 * l0a + p11 * l1a + p12 * l2a;
        v1.y = acc[nt][3] + p10 * l0b + p11 * l1b + p12 * l2b;
        *(float2*)&out[(size_t)(b * 512 + q0 + r0) * 768 + h * 64 + col] = v0;
        *(float2*)&out[(size_t)(b * 512 + q0 + r1) * 768 + h * 64 + col] = v1;
    }
}

// ---------------- launcher ----------------------------------------------------
extern "C" void kernel_launch(void* const* d_in, const int* in_sizes, int n_in,
                              void* d_out, int out_size) {
    const float* hidden = (const float*)d_in[0];
    const float* ctx    = (const float*)d_in[1];
    const float* mask   = (const float*)d_in[2];
    const int*   arc    = (const int*)d_in[3];
    const float* Wq = (const float*)d_in[4];  const float* bq = (const float*)d_in[5];
    const float* Wk = (const float*)d_in[6];  const float* bk = (const float*)d_in[7];
    const float* Wv = (const float*)d_in[8];  const float* bv = (const float*)d_in[9];
    const float* dpk = (const float*)d_in[10]; const float* dpv = (const float*)d_in[11];
    const float* lkg = (const float*)d_in[12]; const float* lkb = (const float*)d_in[13];
    const float* lvg = (const float*)d_in[14]; const float* lvb = (const float*)d_in[15];
    float* out = (float*)d_out;

    prep_kernel<<<5921, 256>>>(arc, hidden, ctx, Wq, Wk, Wv,
                               dpk, dpv, lkg, lkb, lvg, lvb);

    cudaFuncSetAttribute(qkv_gemm_f16_kernel, cudaFuncAttributeMaxDynamicSharedMemorySize,
                         GEMM_SMEM_BYTES);
    qkv_gemm_f16_kernel<<<dim3(16, 6, 3), 256, GEMM_SMEM_BYTES>>>(bq, bk, bv);

    qdp_kernel<<<3072, 256>>>();

    cudaFuncSetAttribute(qk_kernel, cudaFuncAttributeMaxDynamicSharedMemorySize,
                         QK_SMEM_BYTES);
    qk_kernel<<<dim3(4, 4, 48), 256, QK_SMEM_BYTES>>>(mask);

    cudaFuncSetAttribute(pv_kernel, cudaFuncAttributeMaxDynamicSharedMemorySize,
                         PV_SMEM_BYTES);
    pv_kernel<<<dim3(8, 48), 256, PV_SMEM_BYTES>>>(out);
}

// round 16
// speedup vs baseline: 1.1360x; 1.0154x over previous
#include <cuda_runtime.h>
#include <cuda_fp16.h>
#include <cstdint>

#define HNUM 12
#define DHEAD 64
#define BATCH 4
#define LQ 512
#define LK 512
#define DMODEL 768
#define XSIZE (BATCH*LQ*DMODEL)
#define NROWS (BATCH*HNUM*LQ)

// ---------------- scratch (device globals; no runtime alloc) ----------------
__device__ __half g_Xh[2*XSIZE];
__device__ __half g_Wth[3][DMODEL*DMODEL];
__device__ __half g_Qh[BATCH*HNUM*LQ*DHEAD];
__device__ __half g_Kh[BATCH*HNUM*LK*DHEAD];
__device__ __half g_Vth[(size_t)BATCH*HNUM*DHEAD*LK];
__device__ float  g_S[(size_t)BATCH*HNUM*LQ*LK];
__device__ float  g_SUM[NROWS*4];
__device__ float  g_QDP[NROWS*4];
__device__ uint32_t g_arc8[BATCH*512*512/4];
__device__ float  g_lnk[3*DHEAD];
__device__ float  g_lnv[3*DHEAD];

__device__ __forceinline__ uint32_t h2_bits(__half2 h) {
    union { __half2 h; uint32_t u; } cvt;
    cvt.h = h;
    return cvt.u;
}

#define MMA_F16(d, a, b)                                                      \
    asm volatile("mma.sync.aligned.m16n8k16.row.col.f32.f16.f16.f32 "          \
        "{%0,%1,%2,%3}, {%4,%5,%6,%7}, {%8,%9}, {%0,%1,%2,%3};"                \
        : "+f"((d)[0]), "+f"((d)[1]), "+f"((d)[2]), "+f"((d)[3])               \
        : "r"((a)[0]), "r"((a)[1]), "r"((a)[2]), "r"((a)[3]),                  \
          "r"((b)[0]), "r"((b)[1]))

#define LDSM_X4(r, addr)                                                      \
    asm volatile("ldmatrix.sync.aligned.m8n8.x4.shared.b16 {%0,%1,%2,%3}, [%4];" \
        : "=r"((r)[0]), "=r"((r)[1]), "=r"((r)[2]), "=r"((r)[3]) : "r"(addr))

#define CP_ASYNC16(dst, src) \
    asm volatile("cp.async.cg.shared.global [%0], [%1], 16;" :: "r"(dst), "l"(src) : "memory")
#define CP_COMMIT() asm volatile("cp.async.commit_group;" ::: "memory")
#define CP_WAIT1()  asm volatile("cp.async.wait_group 1;" ::: "memory")
#define CP_WAIT0()  asm volatile("cp.async.wait_group 0;" ::: "memory")

// ---------------- K1: arc pack | X cvt | W transpose | zero sums | LN --------
__global__ __launch_bounds__(256) void prep_kernel(
    const int* __restrict__ arc,
    const float* __restrict__ hidden, const float* __restrict__ ctx,
    const float* __restrict__ Wq, const float* __restrict__ Wk,
    const float* __restrict__ Wv,
    const float* __restrict__ dpk, const float* __restrict__ dpv,
    const float* __restrict__ kg, const float* __restrict__ kb,
    const float* __restrict__ vg, const float* __restrict__ vb) {
    int bx = blockIdx.x;
    int t = threadIdx.x;
    if (bx < 1024) {
        int i = bx * 256 + t;
        const int4 a = *(const int4*)&arc[i * 4];
        g_arc8[i] = (uint32_t)a.x | ((uint32_t)a.y << 8) |
                    ((uint32_t)a.z << 16) | ((uint32_t)a.w << 24);
        return;
    }
    if (bx < 4096) {
        bool is_h = bx < 2560;
        const float* src = is_h ? hidden : ctx;
        __half* dst = g_Xh + (is_h ? 0 : XSIZE);
        int i = ((bx - (is_h ? 1024 : 2560)) * 256 + t) * 4;
        float4 v = *(const float4*)&src[i];
        *(__half2*)&dst[i]     = __floats2half2_rn(v.x, v.y);
        *(__half2*)&dst[i + 2] = __floats2half2_rn(v.z, v.w);
        return;
    }
    if (bx < 5824) {
        __shared__ float tile[32][33];
        int wb = bx - 4096;
        int sel = wb / 576;
        int tl = wb % 576;
        int tx0 = (tl % 24) * 32, ty0 = (tl / 24) * 32;
        const float* W = (sel == 0) ? Wq : (sel == 1 ? Wk : Wv);
        __half* WT = g_Wth[sel];
        int tx = t & 31, ty = t >> 5;
        #pragma unroll
        for (int i = 0; i < 32; i += 8)
            tile[ty + i][tx] = W[(size_t)(ty0 + ty + i) * DMODEL + tx0 + tx];
        __syncthreads();
        #pragma unroll
        for (int i = 0; i < 32; i += 8)
            WT[(size_t)(tx0 + ty + i) * DMODEL + ty0 + tx] =
                __float2half_rn(tile[tx][ty + i]);
        return;
    }
    if (bx < 5920) {
        int i = (bx - 5824) * 256 + t;
        *(float4*)&g_SUM[i * 4] = make_float4(0.f, 0.f, 0.f, 0.f);
        return;
    }
    int w = t >> 5;
    int lane = t & 31;
    if (w >= 6) return;
    const float* src = (w < 3) ? dpk + w * DHEAD : dpv + (w - 3) * DHEAD;
    const float* g   = (w < 3) ? kg : vg;
    const float* be  = (w < 3) ? kb : vb;
    float* dst       = (w < 3) ? g_lnk + w * DHEAD : g_lnv + (w - 3) * DHEAD;
    float e0 = src[lane], e1 = src[lane + 32];
    float s = e0 + e1;
    #pragma unroll
    for (int o = 16; o; o >>= 1) s += __shfl_xor_sync(0xffffffffu, s, o);
    float mu = s * (1.0f / 64.0f);
    float d0 = e0 - mu, d1 = e1 - mu;
    float v = d0 * d0 + d1 * d1;
    #pragma unroll
    for (int o = 16; o; o >>= 1) v += __shfl_xor_sync(0xffffffffu, v, o);
    float rs = rsqrtf(v * (1.0f / 64.0f) + 1e-5f);
    dst[lane]      = d0 * rs * g[lane]      + be[lane];
    dst[lane + 32] = d1 * rs * g[lane + 32] + be[lane + 32];
}

// ---------------- K2: f16 mma.sync QKV GEMM (ldmatrix) -----------------------
#define GW 36
#define G_STAGE_W (128 * GW * 2)
#define GEMM_SMEM_BYTES (2 * G_STAGE_W * 4)

__global__ __launch_bounds__(256, 2) void qkv_gemm_f16_kernel(
    const float* __restrict__ bq, const float* __restrict__ bk,
    const float* __restrict__ bv) {
    extern __shared__ uint32_t sm32[];

    int sel = blockIdx.z;
    const __half* Xh = g_Xh + ((sel == 0) ? 0 : XSIZE);
    const __half* Wth = g_Wth[sel];
    const float* bias = (sel == 0) ? bq : (sel == 1 ? bk : bv);

    int m0 = blockIdx.x * 128;
    int n0 = blockIdx.y * 128;
    int t = threadIdx.x;
    int w = t >> 5;
    int lane = t & 31;
    int gid = lane >> 2;
    int tid4 = lane & 3;
    int wm = w >> 2;
    int wn = w & 3;

    auto load_chunk = [&](int c, int s) {
        int k0 = c * 64;
        uint32_t* sA = sm32 + s * G_STAGE_W;
        uint32_t* sB = sA + 128 * GW;
        #pragma unroll
        for (int it = 0; it < 4; it++) {
            int idx = it * 256 + t;
            int r = idx >> 3, c8 = idx & 7;
            uint32_t da = (uint32_t)__cvta_generic_to_shared(&sA[r * GW + c8 * 4]);
            CP_ASYNC16(da, (const char*)(Xh + (size_t)(m0 + r) * DMODEL + k0) + c8 * 16);
            uint32_t db = (uint32_t)__cvta_generic_to_shared(&sB[r * GW + c8 * 4]);
            CP_ASYNC16(db, (const char*)(Wth + (size_t)(n0 + r) * DMODEL + k0) + c8 * 16);
        }
        CP_COMMIT();
    };

    uint32_t sbase = (uint32_t)__cvta_generic_to_shared(sm32);
    int rA = wm * 64 + (lane & 7) + ((lane >> 3) & 1) * 8;
    int wA = (lane >> 4) * 4;
    uint32_t addrA = sbase + (uint32_t)(rA * GW + wA) * 4;
    int rB = wn * 32 + (lane >> 4) * 8 + (lane & 7);
    int wB = ((lane >> 3) & 1) * 4;
    uint32_t addrB = sbase + (uint32_t)(128 * GW + rB * GW + wB) * 4;

    float acc[4][4][4];
    #pragma unroll
    for (int mt = 0; mt < 4; mt++)
        #pragma unroll
        for (int nt = 0; nt < 4; nt++)
            #pragma unroll
            for (int f = 0; f < 4; f++) acc[mt][nt][f] = 0.f;

    load_chunk(0, 0);
    load_chunk(1, 1);
    CP_WAIT1();
    __syncthreads();

    for (int c = 0; c < 12; c++) {
        int s = c & 1;
        uint32_t stOff = (uint32_t)(s * G_STAGE_W) * 4;
        #pragma unroll
        for (int ks = 0; ks < 4; ks++) {
            uint32_t kOff = stOff + ks * 32;
            uint32_t afr[4][4];
            #pragma unroll
            for (int mt = 0; mt < 4; mt++)
                LDSM_X4(afr[mt], addrA + kOff + (uint32_t)(mt * 16 * GW) * 4);
            uint32_t bw[8];
            LDSM_X4(bw,     addrB + kOff);
            LDSM_X4(bw + 4, addrB + kOff + (uint32_t)(16 * GW) * 4);
            #pragma unroll
            for (int nt = 0; nt < 4; nt++)
                #pragma unroll
                for (int mt = 0; mt < 4; mt++)
                    MMA_F16(acc[mt][nt], afr[mt], &bw[nt * 2]);
        }
        __syncthreads();
        if (c + 2 < 12) {
            load_chunk(c + 2, s);
            CP_WAIT1();
        } else {
            CP_WAIT0();
        }
        __syncthreads();
    }

    float bv2[4][2];
    #pragma unroll
    for (int nt = 0; nt < 4; nt++) {
        int col = n0 + wn * 32 + nt * 8 + tid4 * 2;
        bv2[nt][0] = bias[col];
        bv2[nt][1] = bias[col + 1];
    }
    #pragma unroll
    for (int mt = 0; mt < 4; mt++) {
        #pragma unroll
        for (int hf = 0; hf < 2; hf++) {
            int row = m0 + wm * 64 + mt * 16 + gid + hf * 8;
            int b = row >> 9, tok = row & 511;
            #pragma unroll
            for (int nt = 0; nt < 4; nt++) {
                int col = n0 + wn * 32 + nt * 8 + tid4 * 2;
                int head = col >> 6, dh = col & 63;
                float vx = acc[mt][nt][hf * 2 + 0] + bv2[nt][0];
                float vy = acc[mt][nt][hf * 2 + 1] + bv2[nt][1];
                if (sel == 2) {
                    size_t base = ((size_t)(b * HNUM + head) * 64 + dh) * 512 + tok;
                    g_Vth[base]       = __float2half_rn(vx);
                    g_Vth[base + 512] = __float2half_rn(vy);
                } else {
                    __half* Out = (sel == 0) ? g_Qh : g_Kh;
                    *(__half2*)&Out[((size_t)(b * HNUM + head) * 512 + tok) * 64 + dh] =
                        __floats2half2_rn(vx, vy);
                }
            }
        }
    }
}

// ---------------- K2b: qdp[row][r] = Q[row] . lnk[r] -------------------------
__global__ __launch_bounds__(256) void qdp_kernel() {
    int w = blockIdx.x * 8 + (threadIdx.x >> 5);
    int lane = threadIdx.x & 31;
    const __half* Qrow = g_Qh + (size_t)w * 64;
    float q0v = __half2float(Qrow[lane]), q1v = __half2float(Qrow[lane + 32]);
    float s0 = q0v * g_lnk[lane]       + q1v * g_lnk[lane + 32];
    float s1 = q0v * g_lnk[64 + lane]  + q1v * g_lnk[96 + lane];
    float s2 = q0v * g_lnk[128 + lane] + q1v * g_lnk[160 + lane];
    #pragma unroll
    for (int o = 16; o; o >>= 1) {
        s0 += __shfl_xor_sync(0xffffffffu, s0, o);
        s1 += __shfl_xor_sync(0xffffffffu, s1, o);
        s2 += __shfl_xor_sync(0xffffffffu, s2, o);
    }
    if (lane == 0)
        *(float4*)&g_QDP[w * 4] = make_float4(s0, s1, s2, 0.f);
}

// ---------------- KA: E = exp(QK^T/8 + qdp[arc] + mask) + fused sums ---------
// 64q x 128k tiles, 8 warps as 2x4, warp tile m32n32, 3 CTAs/SM.
#define QKW 36
#define QK_SQ_W (64 * QKW)                     // 2304 words
#define QK_SK_W (128 * QKW)                    // 4608 words
#define QK_F32_OFF (QK_SQ_W + QK_SK_W)         // 6912
#define QK_SMEM_BYTES ((QK_F32_OFF + 128 + 256) * 4 + 8192)

__global__ __launch_bounds__(256, 3) void qk_kernel(const float* __restrict__ mask) {
    extern __shared__ uint32_t sm32[];
    uint32_t* sQ = sm32;
    uint32_t* sK = sm32 + QK_SQ_W;
    float* sMask = (float*)(sm32 + QK_F32_OFF);
    float* sQdp  = sMask + 128;                // [64][4]
    unsigned char* sArc = (unsigned char*)(sQdp + 256);   // [64][128]

    int bh = blockIdx.z;
    int b = bh / HNUM;
    int q0 = blockIdx.x * 64;
    int k0 = blockIdx.y * 128;
    int t = threadIdx.x;
    int w = t >> 5;
    int lane = t & 31;
    int gid = lane >> 2;
    int tid4 = lane & 3;
    int wm = w >> 2;        // 0..1 (32-row slab)
    int wn = w & 3;         // 0..3 (32-col slab)

    const __half* Qbase = g_Qh + ((size_t)bh * 512 + q0) * 64;
    const __half* Kbase = g_Kh + ((size_t)bh * 512 + k0) * 64;
    const char* Abase = (const char*)g_arc8 + ((size_t)(b * 512 + q0)) * 512 + k0;

    // Q: 64 rows x 8 chunks = 512
    #pragma unroll
    for (int it = 0; it < 2; it++) {
        int idx = it * 256 + t;
        int r = idx >> 3, c = idx & 7;
        uint32_t dq = (uint32_t)__cvta_generic_to_shared(&sQ[r * QKW + c * 4]);
        CP_ASYNC16(dq, (const char*)(Qbase + (size_t)r * 64) + c * 16);
    }
    // K: 128 rows x 8 chunks = 1024
    #pragma unroll
    for (int it = 0; it < 4; it++) {
        int idx = it * 256 + t;
        int r = idx >> 3, c = idx & 7;
        uint32_t dk = (uint32_t)__cvta_generic_to_shared(&sK[r * QKW + c * 4]);
        CP_ASYNC16(dk, (const char*)(Kbase + (size_t)r * 64) + c * 16);
    }
    // arc: 64 rows x 128B = 512 chunks of 16B
    #pragma unroll
    for (int it = 0; it < 2; it++) {
        int idx = it * 256 + t;
        int r = idx >> 3, c16 = (idx & 7) * 16;
        uint32_t da = (uint32_t)__cvta_generic_to_shared(&sArc[r * 128 + c16]);
        CP_ASYNC16(da, Abase + (size_t)r * 512 + c16);
    }
    CP_COMMIT();
    if (t < 128) sMask[t] = mask[b * 512 + k0 + t];
    if (t < 64)
        *(float4*)&sQdp[t * 4] = *(const float4*)&g_QDP[((size_t)bh * 512 + q0 + t) * 4];
    CP_WAIT0();
    __syncthreads();

    uint32_t sbase = (uint32_t)__cvta_generic_to_shared(sm32);
    int rA = wm * 32 + (lane & 7) + ((lane >> 3) & 1) * 8;
    int wA = (lane >> 4) * 4;
    uint32_t addrA = sbase + (uint32_t)(rA * QKW + wA) * 4;
    int rB = wn * 32 + (lane >> 4) * 8 + (lane & 7);
    int wB = ((lane >> 3) & 1) * 4;
    uint32_t addrB = sbase + (uint32_t)(QK_SQ_W + rB * QKW + wB) * 4;

    float acc[2][4][4];
    #pragma unroll
    for (int mt = 0; mt < 2; mt++)
        #pragma unroll
        for (int nt = 0; nt < 4; nt++)
            #pragma unroll
            for (int f = 0; f < 4; f++) acc[mt][nt][f] = 0.f;

    #pragma unroll
    for (int ks = 0; ks < 4; ks++) {
        uint32_t kOff = ks * 32;
        uint32_t afr[2][4];
        #pragma unroll
        for (int mt = 0; mt < 2; mt++)
            LDSM_X4(afr[mt], addrA + kOff + (uint32_t)(mt * 16 * QKW) * 4);
        uint32_t bw[8];
        LDSM_X4(bw,     addrB + kOff);
        LDSM_X4(bw + 4, addrB + kOff + (uint32_t)(16 * QKW) * 4);
        #pragma unroll
        for (int nt = 0; nt < 4; nt++)
            #pragma unroll
            for (int mt = 0; mt < 2; mt++)
                MMA_F16(acc[mt][nt], afr[mt], &bw[nt * 2]);
    }

    #pragma unroll
    for (int mt = 0; mt < 2; mt++) {
        #pragma unroll
        for (int hf = 0; hf < 2; hf++) {
            int rl = wm * 32 + mt * 16 + gid + hf * 8;
            float* Erow = g_S + ((size_t)bh * 512 + q0 + rl) * 512 + k0;
            float lsum = 0.f, lp1 = 0.f, lp2 = 0.f;
            #pragma unroll
            for (int nt = 0; nt < 4; nt++) {
                int lc = wn * 32 + nt * 8 + tid4 * 2;
                int a0 = sArc[rl * 128 + lc];
                int a1 = sArc[rl * 128 + lc + 1];
                float e0 = __expf(fmaf(acc[mt][nt][hf * 2 + 0], 0.125f,
                                       sQdp[rl * 4 + a0] + sMask[lc]));
                float e1 = __expf(fmaf(acc[mt][nt][hf * 2 + 1], 0.125f,
                                       sQdp[rl * 4 + a1] + sMask[lc + 1]));
                *(float2*)&Erow[lc] = make_float2(e0, e1);
                lsum += e0 + e1;
                lp1 += ((a0 == 1) ? e0 : 0.f) + ((a1 == 1) ? e1 : 0.f);
                lp2 += ((a0 == 2) ? e0 : 0.f) + ((a1 == 2) ? e1 : 0.f);
            }
            lsum += __shfl_xor_sync(0xffffffffu, lsum, 1);
            lsum += __shfl_xor_sync(0xffffffffu, lsum, 2);
            lp1  += __shfl_xor_sync(0xffffffffu, lp1, 1);
            lp1  += __shfl_xor_sync(0xffffffffu, lp1, 2);
            lp2  += __shfl_xor_sync(0xffffffffu, lp2, 1);
            lp2  += __shfl_xor_sync(0xffffffffu, lp2, 2);
            if (tid4 == 0) {
                float* dst = &g_SUM[((size_t)bh * 512 + q0 + rl) * 4];
                atomicAdd(dst + 0, lsum);
                atomicAdd(dst + 1, lp1);
                atomicAdd(dst + 2, lp2);
            }
        }
    }
}

// ---------------- KC: O = (E/sum) V + pw . lnv (ldmatrix) --------------------
#define PVW 20
#define PV_STAGE_W (64 * PVW + 64 * PVW)
#define PV_SMEM_BYTES (2 * PV_STAGE_W * 4)

__global__ __launch_bounds__(256, 4) void pv_kernel(float* __restrict__ out) {
    extern __shared__ uint32_t sm32[];

    int bh = blockIdx.y;
    int b = bh / HNUM, h = bh % HNUM;
    int q0 = blockIdx.x * 64;
    int t = threadIdx.x;
    int w = t >> 5;
    int lane = t & 31;
    int gid = lane >> 2;
    int tid4 = lane & 3;
    int wm = w >> 1;
    int wn = w & 1;

    const float* Ebase = g_S + ((size_t)bh * 512 + q0) * 512;
    const __half* Vtbase = g_Vth + (size_t)bh * 64 * 512;

    int er = t >> 2;
    int ec = (t & 3) * 8;
    float inv_e = 1.f / g_SUM[((size_t)bh * 512 + q0 + er) * 4];

    float4 eA, eB;
    auto loadE = [&](int c) {
        const float* p = Ebase + (size_t)er * 512 + c * 32 + ec;
        eA = *(const float4*)p;
        eB = *(const float4*)(p + 4);
    };
    auto storeE = [&](uint32_t* buf) {
        uint4 v;
        v.x = h2_bits(__floats2half2_rn(eA.x * inv_e, eA.y * inv_e));
        v.y = h2_bits(__floats2half2_rn(eA.z * inv_e, eA.w * inv_e));
        v.z = h2_bits(__floats2half2_rn(eB.x * inv_e, eB.y * inv_e));
        v.w = h2_bits(__floats2half2_rn(eB.z * inv_e, eB.w * inv_e));
        *(uint4*)&buf[er * PVW + (t & 3) * 4] = v;
    };
    auto loadV = [&](int c, uint32_t* buf) {
        int k0 = c * 32;
        uint32_t* sV = buf + 64 * PVW;
        int r = t >> 2, c4 = t & 3;
        uint32_t dv = (uint32_t)__cvta_generic_to_shared(&sV[r * PVW + c4 * 4]);
        CP_ASYNC16(dv, (const char*)(Vtbase + (size_t)r * 512 + k0) + c4 * 16);
        CP_COMMIT();
    };

    uint32_t* buf0 = sm32;
    uint32_t* buf1 = sm32 + PV_STAGE_W;

    uint32_t sbase = (uint32_t)__cvta_generic_to_shared(sm32);
    int rA = wm * 16 + (lane & 7) + ((lane >> 3) & 1) * 8;
    int wA = (lane >> 4) * 4;
    uint32_t addrA = sbase + (uint32_t)(rA * PVW + wA) * 4;
    int rB = wn * 32 + (lane >> 4) * 8 + (lane & 7);
    int wB = ((lane >> 3) & 1) * 4;
    uint32_t addrB = sbase + (uint32_t)(64 * PVW + rB * PVW + wB) * 4;

    float acc[4][4];
    #pragma unroll
    for (int nt = 0; nt < 4; nt++)
        #pragma unroll
        for (int f = 0; f < 4; f++) acc[nt][f] = 0.f;

    loadE(0);
    storeE(buf0);
    loadV(0, buf0);
    loadV(1, buf1);
    loadE(1);
    CP_WAIT1();
    __syncthreads();

    for (int c = 0; c < 16; c++) {
        uint32_t* bufn = (c & 1) ? buf0 : buf1;
        uint32_t* bufc = (c & 1) ? buf1 : buf0;
        uint32_t bOff = (uint32_t)((c & 1) ? PV_STAGE_W * 4 : 0);
        #pragma unroll
        for (int ks = 0; ks < 2; ks++) {
            uint32_t kOff = bOff + ks * 32;
            uint32_t afr[4];
            LDSM_X4(afr, addrA + kOff);
            uint32_t bw[8];
            LDSM_X4(bw,     addrB + kOff);
            LDSM_X4(bw + 4, addrB + kOff + (uint32_t)(16 * PVW) * 4);
            #pragma unroll
            for (int nt = 0; nt < 4; nt++)
                MMA_F16(acc[nt], afr, &bw[nt * 2]);
        }
        __syncthreads();
        if (c + 1 < 16) {
            storeE(bufn);
            if (c + 2 < 16) {
                loadE(c + 2);
                loadV(c + 2, bufc);
                CP_WAIT1();
            } else {
                CP_WAIT0();
            }
            __syncthreads();
        }
    }

    int r0 = wm * 16 + gid, r1 = r0 + 8;
    float4 s0v = *(float4*)&g_SUM[((size_t)bh * 512 + q0 + r0) * 4];
    float4 s1v = *(float4*)&g_SUM[((size_t)bh * 512 + q0 + r1) * 4];
    float inv0 = 1.f / s0v.x, inv1 = 1.f / s1v.x;
    float p01 = s0v.y * inv0, p02 = s0v.z * inv0, p00 = 1.f - p01 - p02;
    float p11 = s1v.y * inv1, p12 = s1v.z * inv1, p10 = 1.f - p11 - p12;
    #pragma unroll
    for (int nt = 0; nt < 4; nt++) {
        int col = wn * 32 + nt * 8 + tid4 * 2;
        float l0a = g_lnv[col],       l0b = g_lnv[col + 1];
        float l1a = g_lnv[64 + col],  l1b = g_lnv[64 + col + 1];
        float l2a = g_lnv[128 + col], l2b = g_lnv[128 + col + 1];
        float2 v0, v1;
        v0.x = acc[nt][0] + p00 * l0a + p01 * l1a + p02 * l2a;
        v0.y = acc[nt][1] + p00 * l0b + p01 * l1b + p02 * l2b;
        v1.x = acc[nt][2] + p10 * l0a + p11 * l1a + p12 * l2a;
        v1.y = acc[nt][3] + p10 * l0b + p11 * l1b + p12 * l2b;
        *(float2*)&out[(size_t)(b * 512 + q0 + r0) * 768 + h * 64 + col] = v0;
        *(float2*)&out[(size_t)(b * 512 + q0 + r1) * 768 + h * 64 + col] = v1;
    }
}

// ---------------- launcher ----------------------------------------------------
extern "C" void kernel_launch(void* const* d_in, const int* in_sizes, int n_in,
                              void* d_out, int out_size) {
    const float* hidden = (const float*)d_in[0];
    const float* ctx    = (const float*)d_in[1];
    const float* mask   = (const float*)d_in[2];
    const int*   arc    = (const int*)d_in[3];
    const float* Wq = (const float*)d_in[4];  const float* bq = (const float*)d_in[5];
    const float* Wk = (const float*)d_in[6];  const float* bk = (const float*)d_in[7];
    const float* Wv = (const float*)d_in[8];  const float* bv = (const float*)d_in[9];
    const float* dpk = (const float*)d_in[10]; const float* dpv = (const float*)d_in[11];
    const float* lkg = (const float*)d_in[12]; const float* lkb = (const float*)d_in[13];
    const float* lvg = (const float*)d_in[14]; const float* lvb = (const float*)d_in[15];
    float* out = (float*)d_out;

    prep_kernel<<<5921, 256>>>(arc, hidden, ctx, Wq, Wk, Wv,
                               dpk, dpv, lkg, lkb, lvg, lvb);

    cudaFuncSetAttribute(qkv_gemm_f16_kernel, cudaFuncAttributeMaxDynamicSharedMemorySize,
                         GEMM_SMEM_BYTES);
    qkv_gemm_f16_kernel<<<dim3(16, 6, 3), 256, GEMM_SMEM_BYTES>>>(bq, bk, bv);

    qdp_kernel<<<3072, 256>>>();

    cudaFuncSetAttribute(qk_kernel, cudaFuncAttributeMaxDynamicSharedMemorySize,
                         QK_SMEM_BYTES);
    qk_kernel<<<dim3(8, 4, 48), 256, QK_SMEM_BYTES>>>(mask);

    cudaFuncSetAttribute(pv_kernel, cudaFuncAttributeMaxDynamicSharedMemorySize,
                         PV_SMEM_BYTES);
    pv_kernel<<<dim3(8, 48), 256, PV_SMEM_BYTES>>>(out);
}

// round 17
// speedup vs baseline: 1.2054x; 1.0611x over previous
#include <cuda_runtime.h>
#include <cuda_fp16.h>
#include <cuda_bf16.h>
#include <cstdint>

#define HNUM 12
#define DHEAD 64
#define BATCH 4
#define LQ 512
#define LK 512
#define DMODEL 768
#define XSIZE (BATCH*LQ*DMODEL)
#define NROWS (BATCH*HNUM*LQ)
#define LOG2E 1.4426950408889634f

// ---------------- scratch (device globals; no runtime alloc) ----------------
__device__ __half g_Xh[2*XSIZE];
__device__ __half g_Wth[3][DMODEL*DMODEL];
__device__ __half g_Qh[BATCH*HNUM*LQ*DHEAD];
__device__ __half g_Kh[BATCH*HNUM*LK*DHEAD];
__device__ __nv_bfloat16 g_Vtb[(size_t)BATCH*HNUM*DHEAD*LK];   // [bh][d][tok]
__device__ __nv_bfloat16 g_E[(size_t)BATCH*HNUM*LQ*LK];        // unnormalized exp
__device__ float  g_SUM[NROWS*4];
__device__ float  g_QDP[NROWS*4];                              // pre-scaled by log2e
__device__ uint32_t g_arc8[BATCH*512*512/4];
__device__ float  g_lnk[3*DHEAD];
__device__ float  g_lnv[3*DHEAD];

__device__ __forceinline__ float ex2f(float x) {
    float r;
    asm("ex2.approx.f32 %0, %1;" : "=f"(r) : "f"(x));
    return r;
}

#define MMA_F16(d, a, b)                                                      \
    asm volatile("mma.sync.aligned.m16n8k16.row.col.f32.f16.f16.f32 "          \
        "{%0,%1,%2,%3}, {%4,%5,%6,%7}, {%8,%9}, {%0,%1,%2,%3};"                \
        : "+f"((d)[0]), "+f"((d)[1]), "+f"((d)[2]), "+f"((d)[3])               \
        : "r"((a)[0]), "r"((a)[1]), "r"((a)[2]), "r"((a)[3]),                  \
          "r"((b)[0]), "r"((b)[1]))

#define MMA_BF16(d, a, b)                                                     \
    asm volatile("mma.sync.aligned.m16n8k16.row.col.f32.bf16.bf16.f32 "        \
        "{%0,%1,%2,%3}, {%4,%5,%6,%7}, {%8,%9}, {%0,%1,%2,%3};"                \
        : "+f"((d)[0]), "+f"((d)[1]), "+f"((d)[2]), "+f"((d)[3])               \
        : "r"((a)[0]), "r"((a)[1]), "r"((a)[2]), "r"((a)[3]),                  \
          "r"((b)[0]), "r"((b)[1]))

#define LDSM_X4(r, addr)                                                      \
    asm volatile("ldmatrix.sync.aligned.m8n8.x4.shared.b16 {%0,%1,%2,%3}, [%4];" \
        : "=r"((r)[0]), "=r"((r)[1]), "=r"((r)[2]), "=r"((r)[3]) : "r"(addr))

#define CP_ASYNC16(dst, src) \
    asm volatile("cp.async.cg.shared.global [%0], [%1], 16;" :: "r"(dst), "l"(src) : "memory")
#define CP_COMMIT() asm volatile("cp.async.commit_group;" ::: "memory")
#define CP_WAIT1()  asm volatile("cp.async.wait_group 1;" ::: "memory")
#define CP_WAIT0()  asm volatile("cp.async.wait_group 0;" ::: "memory")

// ---------------- K1: arc pack | X cvt | W transpose | zero sums | LN --------
__global__ __launch_bounds__(256) void prep_kernel(
    const int* __restrict__ arc,
    const float* __restrict__ hidden, const float* __restrict__ ctx,
    const float* __restrict__ Wq, const float* __restrict__ Wk,
    const float* __restrict__ Wv,
    const float* __restrict__ dpk, const float* __restrict__ dpv,
    const float* __restrict__ kg, const float* __restrict__ kb,
    const float* __restrict__ vg, const float* __restrict__ vb) {
    int bx = blockIdx.x;
    int t = threadIdx.x;
    if (bx < 1024) {
        int i = bx * 256 + t;
        const int4 a = *(const int4*)&arc[i * 4];
        g_arc8[i] = (uint32_t)a.x | ((uint32_t)a.y << 8) |
                    ((uint32_t)a.z << 16) | ((uint32_t)a.w << 24);
        return;
    }
    if (bx < 4096) {
        bool is_h = bx < 2560;
        const float* src = is_h ? hidden : ctx;
        __half* dst = g_Xh + (is_h ? 0 : XSIZE);
        int i = ((bx - (is_h ? 1024 : 2560)) * 256 + t) * 4;
        float4 v = *(const float4*)&src[i];
        *(__half2*)&dst[i]     = __floats2half2_rn(v.x, v.y);
        *(__half2*)&dst[i + 2] = __floats2half2_rn(v.z, v.w);
        return;
    }
    if (bx < 5824) {
        __shared__ float tile[32][33];
        int wb = bx - 4096;
        int sel = wb / 576;
        int tl = wb % 576;
        int tx0 = (tl % 24) * 32, ty0 = (tl / 24) * 32;
        const float* W = (sel == 0) ? Wq : (sel == 1 ? Wk : Wv);
        __half* WT = g_Wth[sel];
        int tx = t & 31, ty = t >> 5;
        #pragma unroll
        for (int i = 0; i < 32; i += 8)
            tile[ty + i][tx] = W[(size_t)(ty0 + ty + i) * DMODEL + tx0 + tx];
        __syncthreads();
        #pragma unroll
        for (int i = 0; i < 32; i += 8)
            WT[(size_t)(tx0 + ty + i) * DMODEL + ty0 + tx] =
                __float2half_rn(tile[tx][ty + i]);
        return;
    }
    if (bx < 5920) {
        int i = (bx - 5824) * 256 + t;
        *(float4*)&g_SUM[i * 4] = make_float4(0.f, 0.f, 0.f, 0.f);
        return;
    }
    int w = t >> 5;
    int lane = t & 31;
    if (w >= 6) return;
    const float* src = (w < 3) ? dpk + w * DHEAD : dpv + (w - 3) * DHEAD;
    const float* g   = (w < 3) ? kg : vg;
    const float* be  = (w < 3) ? kb : vb;
    float* dst       = (w < 3) ? g_lnk + w * DHEAD : g_lnv + (w - 3) * DHEAD;
    float e0 = src[lane], e1 = src[lane + 32];
    float s = e0 + e1;
    #pragma unroll
    for (int o = 16; o; o >>= 1) s += __shfl_xor_sync(0xffffffffu, s, o);
    float mu = s * (1.0f / 64.0f);
    float d0 = e0 - mu, d1 = e1 - mu;
    float v = d0 * d0 + d1 * d1;
    #pragma unroll
    for (int o = 16; o; o >>= 1) v += __shfl_xor_sync(0xffffffffu, v, o);
    float rs = rsqrtf(v * (1.0f / 64.0f) + 1e-5f);
    dst[lane]      = d0 * rs * g[lane]      + be[lane];
    dst[lane + 32] = d1 * rs * g[lane + 32] + be[lane + 32];
}

// ---------------- K2: f16 mma.sync QKV GEMM (ldmatrix) -----------------------
#define GW 36
#define G_STAGE_W (128 * GW * 2)
#define GEMM_SMEM_BYTES (2 * G_STAGE_W * 4)

__global__ __launch_bounds__(256, 2) void qkv_gemm_f16_kernel(
    const float* __restrict__ bq, const float* __restrict__ bk,
    const float* __restrict__ bv) {
    extern __shared__ uint32_t sm32[];

    int sel = blockIdx.z;
    const __half* Xh = g_Xh + ((sel == 0) ? 0 : XSIZE);
    const __half* Wth = g_Wth[sel];
    const float* bias = (sel == 0) ? bq : (sel == 1 ? bk : bv);

    int m0 = blockIdx.x * 128;
    int n0 = blockIdx.y * 128;
    int t = threadIdx.x;
    int w = t >> 5;
    int lane = t & 31;
    int gid = lane >> 2;
    int tid4 = lane & 3;
    int wm = w >> 2;
    int wn = w & 3;

    auto load_chunk = [&](int c, int s) {
        int k0 = c * 64;
        uint32_t* sA = sm32 + s * G_STAGE_W;
        uint32_t* sB = sA + 128 * GW;
        #pragma unroll
        for (int it = 0; it < 4; it++) {
            int idx = it * 256 + t;
            int r = idx >> 3, c8 = idx & 7;
            uint32_t da = (uint32_t)__cvta_generic_to_shared(&sA[r * GW + c8 * 4]);
            CP_ASYNC16(da, (const char*)(Xh + (size_t)(m0 + r) * DMODEL + k0) + c8 * 16);
            uint32_t db = (uint32_t)__cvta_generic_to_shared(&sB[r * GW + c8 * 4]);
            CP_ASYNC16(db, (const char*)(Wth + (size_t)(n0 + r) * DMODEL + k0) + c8 * 16);
        }
        CP_COMMIT();
    };

    uint32_t sbase = (uint32_t)__cvta_generic_to_shared(sm32);
    int rA = wm * 64 + (lane & 7) + ((lane >> 3) & 1) * 8;
    int wA = (lane >> 4) * 4;
    uint32_t addrA = sbase + (uint32_t)(rA * GW + wA) * 4;
    int rB = wn * 32 + (lane >> 4) * 8 + (lane & 7);
    int wB = ((lane >> 3) & 1) * 4;
    uint32_t addrB = sbase + (uint32_t)(128 * GW + rB * GW + wB) * 4;

    float acc[4][4][4];
    #pragma unroll
    for (int mt = 0; mt < 4; mt++)
        #pragma unroll
        for (int nt = 0; nt < 4; nt++)
            #pragma unroll
            for (int f = 0; f < 4; f++) acc[mt][nt][f] = 0.f;

    load_chunk(0, 0);
    load_chunk(1, 1);
    CP_WAIT1();
    __syncthreads();

    for (int c = 0; c < 12; c++) {
        int s = c & 1;
        uint32_t stOff = (uint32_t)(s * G_STAGE_W) * 4;
        #pragma unroll
        for (int ks = 0; ks < 4; ks++) {
            uint32_t kOff = stOff + ks * 32;
            uint32_t afr[4][4];
            #pragma unroll
            for (int mt = 0; mt < 4; mt++)
                LDSM_X4(afr[mt], addrA + kOff + (uint32_t)(mt * 16 * GW) * 4);
            uint32_t bw[8];
            LDSM_X4(bw,     addrB + kOff);
            LDSM_X4(bw + 4, addrB + kOff + (uint32_t)(16 * GW) * 4);
            #pragma unroll
            for (int nt = 0; nt < 4; nt++)
                #pragma unroll
                for (int mt = 0; mt < 4; mt++)
                    MMA_F16(acc[mt][nt], afr[mt], &bw[nt * 2]);
        }
        __syncthreads();
        if (c + 2 < 12) {
            load_chunk(c + 2, s);
            CP_WAIT1();
        } else {
            CP_WAIT0();
        }
        __syncthreads();
    }

    float bv2[4][2];
    #pragma unroll
    for (int nt = 0; nt < 4; nt++) {
        int col = n0 + wn * 32 + nt * 8 + tid4 * 2;
        bv2[nt][0] = bias[col];
        bv2[nt][1] = bias[col + 1];
    }
    #pragma unroll
    for (int mt = 0; mt < 4; mt++) {
        #pragma unroll
        for (int hf = 0; hf < 2; hf++) {
            int row = m0 + wm * 64 + mt * 16 + gid + hf * 8;
            int b = row >> 9, tok = row & 511;
            #pragma unroll
            for (int nt = 0; nt < 4; nt++) {
                int col = n0 + wn * 32 + nt * 8 + tid4 * 2;
                int head = col >> 6, dh = col & 63;
                float vx = acc[mt][nt][hf * 2 + 0] + bv2[nt][0];
                float vy = acc[mt][nt][hf * 2 + 1] + bv2[nt][1];
                if (sel == 2) {
                    size_t base = ((size_t)(b * HNUM + head) * 64 + dh) * 512 + tok;
                    g_Vtb[base]       = __float2bfloat16(vx);
                    g_Vtb[base + 512] = __float2bfloat16(vy);
                } else {
                    __half* Out = (sel == 0) ? g_Qh : g_Kh;
                    *(__half2*)&Out[((size_t)(b * HNUM + head) * 512 + tok) * 64 + dh] =
                        __floats2half2_rn(vx, vy);
                }
            }
        }
    }
}

// ---------------- K2b: qdp[row][r] = (Q[row] . lnk[r]) * log2e ---------------
__global__ __launch_bounds__(256) void qdp_kernel() {
    int w = blockIdx.x * 8 + (threadIdx.x >> 5);
    int lane = threadIdx.x & 31;
    const __half* Qrow = g_Qh + (size_t)w * 64;
    float q0v = __half2float(Qrow[lane]), q1v = __half2float(Qrow[lane + 32]);
    float s0 = q0v * g_lnk[lane]       + q1v * g_lnk[lane + 32];
    float s1 = q0v * g_lnk[64 + lane]  + q1v * g_lnk[96 + lane];
    float s2 = q0v * g_lnk[128 + lane] + q1v * g_lnk[160 + lane];
    #pragma unroll
    for (int o = 16; o; o >>= 1) {
        s0 += __shfl_xor_sync(0xffffffffu, s0, o);
        s1 += __shfl_xor_sync(0xffffffffu, s1, o);
        s2 += __shfl_xor_sync(0xffffffffu, s2, o);
    }
    if (lane == 0)
        *(float4*)&g_QDP[w * 4] =
            make_float4(s0 * LOG2E, s1 * LOG2E, s2 * LOG2E, 0.f);
}

// ---------------- KA: E = 2^((QK^T/8 + qdp[arc] + mask)*log2e), bf16 ---------
#define QKW 36
#define QK_SQ_W (64 * QKW)
#define QK_SK_W (128 * QKW)
#define QK_F32_OFF (QK_SQ_W + QK_SK_W)
#define QK_SMEM_BYTES ((QK_F32_OFF + 128 + 256) * 4 + 8192)

__global__ __launch_bounds__(256, 3) void qk_kernel(const float* __restrict__ mask) {
    extern __shared__ uint32_t sm32[];
    uint32_t* sQ = sm32;
    uint32_t* sK = sm32 + QK_SQ_W;
    float* sMask = (float*)(sm32 + QK_F32_OFF);
    float* sQdp  = sMask + 128;
    unsigned char* sArc = (unsigned char*)(sQdp + 256);

    int bh = blockIdx.z;
    int b = bh / HNUM;
    int q0 = blockIdx.x * 64;
    int k0 = blockIdx.y * 128;
    int t = threadIdx.x;
    int w = t >> 5;
    int lane = t & 31;
    int gid = lane >> 2;
    int tid4 = lane & 3;
    int wm = w >> 2;
    int wn = w & 3;

    const __half* Qbase = g_Qh + ((size_t)bh * 512 + q0) * 64;
    const __half* Kbase = g_Kh + ((size_t)bh * 512 + k0) * 64;
    const char* Abase = (const char*)g_arc8 + ((size_t)(b * 512 + q0)) * 512 + k0;

    #pragma unroll
    for (int it = 0; it < 2; it++) {
        int idx = it * 256 + t;
        int r = idx >> 3, c = idx & 7;
        uint32_t dq = (uint32_t)__cvta_generic_to_shared(&sQ[r * QKW + c * 4]);
        CP_ASYNC16(dq, (const char*)(Qbase + (size_t)r * 64) + c * 16);
    }
    #pragma unroll
    for (int it = 0; it < 4; it++) {
        int idx = it * 256 + t;
        int r = idx >> 3, c = idx & 7;
        uint32_t dk = (uint32_t)__cvta_generic_to_shared(&sK[r * QKW + c * 4]);
        CP_ASYNC16(dk, (const char*)(Kbase + (size_t)r * 64) + c * 16);
    }
    #pragma unroll
    for (int it = 0; it < 2; it++) {
        int idx = it * 256 + t;
        int r = idx >> 3, c16 = (idx & 7) * 16;
        uint32_t da = (uint32_t)__cvta_generic_to_shared(&sArc[r * 128 + c16]);
        CP_ASYNC16(da, Abase + (size_t)r * 512 + c16);
    }
    CP_COMMIT();
    if (t < 128) sMask[t] = mask[b * 512 + k0 + t] * LOG2E;
    if (t < 64)
        *(float4*)&sQdp[t * 4] = *(const float4*)&g_QDP[((size_t)bh * 512 + q0 + t) * 4];
    CP_WAIT0();
    __syncthreads();

    uint32_t sbase = (uint32_t)__cvta_generic_to_shared(sm32);
    int rA = wm * 32 + (lane & 7) + ((lane >> 3) & 1) * 8;
    int wA = (lane >> 4) * 4;
    uint32_t addrA = sbase + (uint32_t)(rA * QKW + wA) * 4;
    int rB = wn * 32 + (lane >> 4) * 8 + (lane & 7);
    int wB = ((lane >> 3) & 1) * 4;
    uint32_t addrB = sbase + (uint32_t)(QK_SQ_W + rB * QKW + wB) * 4;

    float acc[2][4][4];
    #pragma unroll
    for (int mt = 0; mt < 2; mt++)
        #pragma unroll
        for (int nt = 0; nt < 4; nt++)
            #pragma unroll
            for (int f = 0; f < 4; f++) acc[mt][nt][f] = 0.f;

    #pragma unroll
    for (int ks = 0; ks < 4; ks++) {
        uint32_t kOff = ks * 32;
        uint32_t afr[2][4];
        #pragma unroll
        for (int mt = 0; mt < 2; mt++)
            LDSM_X4(afr[mt], addrA + kOff + (uint32_t)(mt * 16 * QKW) * 4);
        uint32_t bw[8];
        LDSM_X4(bw,     addrB + kOff);
        LDSM_X4(bw + 4, addrB + kOff + (uint32_t)(16 * QKW) * 4);
        #pragma unroll
        for (int nt = 0; nt < 4; nt++)
            #pragma unroll
            for (int mt = 0; mt < 2; mt++)
                MMA_F16(acc[mt][nt], afr[mt], &bw[nt * 2]);
    }

    const float SC = 0.125f * LOG2E;
    #pragma unroll
    for (int mt = 0; mt < 2; mt++) {
        #pragma unroll
        for (int hf = 0; hf < 2; hf++) {
            int rl = wm * 32 + mt * 16 + gid + hf * 8;
            __nv_bfloat16* Erow = g_E + ((size_t)bh * 512 + q0 + rl) * 512 + k0;
            float lsum = 0.f, lp1 = 0.f, lp2 = 0.f;
            #pragma unroll
            for (int nt = 0; nt < 4; nt++) {
                int lc = wn * 32 + nt * 8 + tid4 * 2;
                unsigned short aw = *(const unsigned short*)&sArc[rl * 128 + lc];
                int a0 = aw & 0xFF;
                int a1 = aw >> 8;
                float2 mv = *(const float2*)&sMask[lc];
                float e0 = ex2f(fmaf(acc[mt][nt][hf * 2 + 0], SC, sQdp[rl * 4 + a0] + mv.x));
                float e1 = ex2f(fmaf(acc[mt][nt][hf * 2 + 1], SC, sQdp[rl * 4 + a1] + mv.y));
                __nv_bfloat162 eh = __floats2bfloat162_rn(e0, e1);
                *(__nv_bfloat162*)&Erow[lc] = eh;
                lsum += e0 + e1;
                lp1 += ((a0 == 1) ? e0 : 0.f) + ((a1 == 1) ? e1 : 0.f);
                lp2 += ((a0 == 2) ? e0 : 0.f) + ((a1 == 2) ? e1 : 0.f);
            }
            lsum += __shfl_xor_sync(0xffffffffu, lsum, 1);
            lsum += __shfl_xor_sync(0xffffffffu, lsum, 2);
            lp1  += __shfl_xor_sync(0xffffffffu, lp1, 1);
            lp1  += __shfl_xor_sync(0xffffffffu, lp1, 2);
            lp2  += __shfl_xor_sync(0xffffffffu, lp2, 1);
            lp2  += __shfl_xor_sync(0xffffffffu, lp2, 2);
            if (tid4 == 0) {
                float* dst = &g_SUM[((size_t)bh * 512 + q0 + rl) * 4];
                atomicAdd(dst + 0, lsum);
                atomicAdd(dst + 1, lp1);
                atomicAdd(dst + 2, lp2);
            }
        }
    }
}

// ---------------- KC: O = (E V)*inv + pw . lnv  (bf16 mma) -------------------
#define PVW 20
#define PV_STAGE_W (64 * PVW + 64 * PVW)
#define PV_SMEM_BYTES (2 * PV_STAGE_W * 4)

__global__ __launch_bounds__(256, 4) void pv_kernel(float* __restrict__ out) {
    extern __shared__ uint32_t sm32[];

    int bh = blockIdx.y;
    int b = bh / HNUM, h = bh % HNUM;
    int q0 = blockIdx.x * 64;
    int t = threadIdx.x;
    int w = t >> 5;
    int lane = t & 31;
    int gid = lane >> 2;
    int tid4 = lane & 3;
    int wm = w >> 1;
    int wn = w & 1;

    const __nv_bfloat16* Ebase = g_E + ((size_t)bh * 512 + q0) * 512;
    const __nv_bfloat16* Vtbase = g_Vtb + (size_t)bh * 64 * 512;

    auto load_chunk = [&](int c, int s) {
        int k0 = c * 32;
        uint32_t* sP = sm32 + s * PV_STAGE_W;
        uint32_t* sV = sP + 64 * PVW;
        int r = t >> 2, c4 = t & 3;
        uint32_t dp = (uint32_t)__cvta_generic_to_shared(&sP[r * PVW + c4 * 4]);
        CP_ASYNC16(dp, (const char*)(Ebase + (size_t)r * 512 + k0) + c4 * 16);
        uint32_t dv = (uint32_t)__cvta_generic_to_shared(&sV[r * PVW + c4 * 4]);
        CP_ASYNC16(dv, (const char*)(Vtbase + (size_t)r * 512 + k0) + c4 * 16);
        CP_COMMIT();
    };

    uint32_t sbase = (uint32_t)__cvta_generic_to_shared(sm32);
    int rA = wm * 16 + (lane & 7) + ((lane >> 3) & 1) * 8;
    int wA = (lane >> 4) * 4;
    uint32_t addrA = sbase + (uint32_t)(rA * PVW + wA) * 4;
    int rB = wn * 32 + (lane >> 4) * 8 + (lane & 7);
    int wB = ((lane >> 3) & 1) * 4;
    uint32_t addrB = sbase + (uint32_t)(64 * PVW + rB * PVW + wB) * 4;

    float acc[4][4];
    #pragma unroll
    for (int nt = 0; nt < 4; nt++)
        #pragma unroll
        for (int f = 0; f < 4; f++) acc[nt][f] = 0.f;

    load_chunk(0, 0);
    load_chunk(1, 1);
    CP_WAIT1();
    __syncthreads();

    for (int c = 0; c < 16; c++) {
        uint32_t bOff = (uint32_t)((c & 1) ? PV_STAGE_W * 4 : 0);
        #pragma unroll
        for (int ks = 0; ks < 2; ks++) {
            uint32_t kOff = bOff + ks * 32;
            uint32_t afr[4];
            LDSM_X4(afr, addrA + kOff);
            uint32_t bw[8];
            LDSM_X4(bw,     addrB + kOff);
            LDSM_X4(bw + 4, addrB + kOff + (uint32_t)(16 * PVW) * 4);
            #pragma unroll
            for (int nt = 0; nt < 4; nt++)
                MMA_BF16(acc[nt], afr, &bw[nt * 2]);
        }
        __syncthreads();
        if (c + 2 < 16) {
            load_chunk(c + 2, c & 1);
            CP_WAIT1();
        } else {
            CP_WAIT0();
        }
        __syncthreads();
    }

    int r0 = wm * 16 + gid, r1 = r0 + 8;
    float4 s0v = *(float4*)&g_SUM[((size_t)bh * 512 + q0 + r0) * 4];
    float4 s1v = *(float4*)&g_SUM[((size_t)bh * 512 + q0 + r1) * 4];
    float inv0 = 1.f / s0v.x, inv1 = 1.f / s1v.x;
    float p01 = s0v.y * inv0, p02 = s0v.z * inv0, p00 = 1.f - p01 - p02;
    float p11 = s1v.y * inv1, p12 = s1v.z * inv1, p10 = 1.f - p11 - p12;
    #pragma unroll
    for (int nt = 0; nt < 4; nt++) {
        int col = wn * 32 + nt * 8 + tid4 * 2;
        float l0a = g_lnv[col],       l0b = g_lnv[col + 1];
        float l1a = g_lnv[64 + col],  l1b = g_lnv[64 + col + 1];
        float l2a = g_lnv[128 + col], l2b = g_lnv[128 + col + 1];
        float2 v0, v1;
        v0.x = acc[nt][0] * inv0 + p00 * l0a + p01 * l1a + p02 * l2a;
        v0.y = acc[nt][1] * inv0 + p00 * l0b + p01 * l1b + p02 * l2b;
        v1.x = acc[nt][2] * inv1 + p10 * l0a + p11 * l1a + p12 * l2a;
        v1.y = acc[nt][3] * inv1 + p10 * l0b + p11 * l1b + p12 * l2b;
        *(float2*)&out[(size_t)(b * 512 + q0 + r0) * 768 + h * 64 + col] = v0;
        *(float2*)&out[(size_t)(b * 512 + q0 + r1) * 768 + h * 64 + col] = v1;
    }
}

// ---------------- launcher ----------------------------------------------------
extern "C" void kernel_launch(void* const* d_in, const int* in_sizes, int n_in,
                              void* d_out, int out_size) {
    const float* hidden = (const float*)d_in[0];
    const float* ctx    = (const float*)d_in[1];
    const float* mask   = (const float*)d_in[2];
    const int*   arc    = (const int*)d_in[3];
    const float* Wq = (const float*)d_in[4];  const float* bq = (const float*)d_in[5];
    const float* Wk = (const float*)d_in[6];  const float* bk = (const float*)d_in[7];
    const float* Wv = (const float*)d_in[8];  const float* bv = (const float*)d_in[9];
    const float* dpk = (const float*)d_in[10]; const float* dpv = (const float*)d_in[11];
    const float* lkg = (const float*)d_in[12]; const float* lkb = (const float*)d_in[13];
    const float* lvg = (const float*)d_in[14]; const float* lvb = (const float*)d_in[15];
    float* out = (float*)d_out;

    prep_kernel<<<5921, 256>>>(arc, hidden, ctx, Wq, Wk, Wv,
                               dpk, dpv, lkg, lkb, lvg, lvb);

    cudaFuncSetAttribute(qkv_gemm_f16_kernel, cudaFuncAttributeMaxDynamicSharedMemorySize,
                         GEMM_SMEM_BYTES);
    qkv_gemm_f16_kernel<<<dim3(16, 6, 3), 256, GEMM_SMEM_BYTES>>>(bq, bk, bv);

    qdp_kernel<<<3072, 256>>>();

    cudaFuncSetAttribute(qk_kernel, cudaFuncAttributeMaxDynamicSharedMemorySize,
                         QK_SMEM_BYTES);
    qk_kernel<<<dim3(8, 4, 48), 256, QK_SMEM_BYTES>>>(mask);

    cudaFuncSetAttribute(pv_kernel, cudaFuncAttributeMaxDynamicSharedMemorySize,
                         PV_SMEM_BYTES);
    pv_kernel<<<dim3(8, 48), 256, PV_SMEM_BYTES>>>(out);
}